// round 5
// baseline (speedup 1.0000x reference)
#include <cuda_runtime.h>
#include <cstdint>

#define D 2048
#define NROWS 4096     // B*S
#define NHEADS 32
#define HDIM 64
#define SEQ 1024
#define NBATCH 4

// Scratch (allocation-free rule: __device__ globals)
__device__ float g_h  [NROWS * D];       // tf32-rounded LN1 output
__device__ float g_x2 [NROWS * D];       // exact h + x residual
__device__ float g_qk [NROWS * 2 * D];   // tf32-rounded [q | k], row stride 4096
__device__ float g_h2 [NROWS * D];       // tf32-rounded LN2 output
__device__ float g_t  [NROWS * D];       // tf32-rounded relu(ff1)
__device__ float g_wqkt[2 * D * D];      // [Wq^T ; Wk^T] K-major, tf32-rounded
__device__ float g_f1t[D * D];
__device__ float g_f2t[D * D];

// ===========================================================================
// Helpers
// ===========================================================================
__device__ __forceinline__ uint32_t smem_u32(const void* p) {
    uint32_t a;
    asm("{ .reg .u64 t; cvta.to.shared.u64 t, %1; cvt.u32.u64 %0, t; }" : "=r"(a) : "l"(p));
    return a;
}
__device__ __forceinline__ float tf32r(float x) {
    uint32_t u;
    asm("cvt.rna.tf32.f32 %0, %1;" : "=r"(u) : "f"(x));
    return __uint_as_float(u);
}
__device__ __forceinline__ void mma_tf32(float* c, uint32_t a0, uint32_t a1,
                                         uint32_t a2, uint32_t a3,
                                         uint32_t b0, uint32_t b1) {
    asm volatile(
        "mma.sync.aligned.m16n8k8.row.col.f32.tf32.tf32.f32 "
        "{%0,%1,%2,%3}, {%4,%5,%6,%7}, {%8,%9}, {%0,%1,%2,%3};"
        : "+f"(c[0]), "+f"(c[1]), "+f"(c[2]), "+f"(c[3])
        : "r"(a0), "r"(a1), "r"(a2), "r"(a3), "r"(b0), "r"(b1));
}
__device__ __forceinline__ void ldsm_x4(uint32_t& r0, uint32_t& r1,
                                        uint32_t& r2, uint32_t& r3, uint32_t addr) {
    asm volatile("ldmatrix.sync.aligned.m8n8.x4.shared.b16 {%0,%1,%2,%3}, [%4];"
        : "=r"(r0), "=r"(r1), "=r"(r2), "=r"(r3) : "r"(addr));
}
#define CP_ASYNC16(smem_addr, gptr) \
    asm volatile("cp.async.cg.shared.global [%0], [%1], 16;" :: "r"(smem_addr), "l"(gptr) : "memory")
#define CP_COMMIT() asm volatile("cp.async.commit_group;" ::: "memory")
#define CP_WAIT(n)  asm volatile("cp.async.wait_group %0;" :: "n"(n) : "memory")

// ===========================================================================
// Block reductions (256 threads)
// ===========================================================================
__device__ __forceinline__ float blockReduceSum256(float v, float* sh) {
    int tid = threadIdx.x;
    #pragma unroll
    for (int o = 16; o > 0; o >>= 1) v += __shfl_xor_sync(0xffffffffu, v, o);
    if ((tid & 31) == 0) sh[tid >> 5] = v;
    __syncthreads();
    if (tid < 8) {
        float w = sh[tid];
        #pragma unroll
        for (int o = 4; o > 0; o >>= 1) w += __shfl_xor_sync(0xffu, w, o);
        if (tid == 0) sh[0] = w;
    }
    __syncthreads();
    float r = sh[0];
    __syncthreads();
    return r;
}

// ===========================================================================
// LayerNorm
// ===========================================================================
__global__ __launch_bounds__(256) void ln_kernel(
    const float* __restrict__ x, const float* __restrict__ scale,
    const float* __restrict__ bias, float* __restrict__ out_h,
    float* __restrict__ out_x2)
{
    __shared__ float sh[8];
    int row = blockIdx.x;
    int tid = threadIdx.x;
    const float4* xr = (const float4*)(x + (size_t)row * D);
    float4 v0 = xr[tid];
    float4 v1 = xr[tid + 256];
    float s = v0.x + v0.y + v0.z + v0.w + v1.x + v1.y + v1.z + v1.w;
    float mean = blockReduceSum256(s, sh) * (1.0f / (float)D);

    float d0x = v0.x - mean, d0y = v0.y - mean, d0z = v0.z - mean, d0w = v0.w - mean;
    float d1x = v1.x - mean, d1y = v1.y - mean, d1z = v1.z - mean, d1w = v1.w - mean;
    float ss = d0x*d0x + d0y*d0y + d0z*d0z + d0w*d0w
             + d1x*d1x + d1y*d1y + d1z*d1z + d1w*d1w;
    float var = blockReduceSum256(ss, sh) * (1.0f / (float)D);
    float inv = rsqrtf(var + 1e-5f);

    const float4* sc = (const float4*)scale;
    const float4* bi = (const float4*)bias;
    float4 s0 = sc[tid], s1 = sc[tid + 256];
    float4 b0 = bi[tid], b1 = bi[tid + 256];

    float4 h0, h1;
    h0.x = d0x * inv * s0.x + b0.x;  h0.y = d0y * inv * s0.y + b0.y;
    h0.z = d0z * inv * s0.z + b0.z;  h0.w = d0w * inv * s0.w + b0.w;
    h1.x = d1x * inv * s1.x + b1.x;  h1.y = d1y * inv * s1.y + b1.y;
    h1.z = d1z * inv * s1.z + b1.z;  h1.w = d1w * inv * s1.w + b1.w;

    float4 r0, r1;
    r0.x = tf32r(h0.x); r0.y = tf32r(h0.y); r0.z = tf32r(h0.z); r0.w = tf32r(h0.w);
    r1.x = tf32r(h1.x); r1.y = tf32r(h1.y); r1.z = tf32r(h1.z); r1.w = tf32r(h1.w);
    float4* hr = (float4*)(out_h + (size_t)row * D);
    hr[tid] = r0;
    hr[tid + 256] = r1;

    if (out_x2) {
        float4 e0, e1;
        e0.x = h0.x + v0.x; e0.y = h0.y + v0.y; e0.z = h0.z + v0.z; e0.w = h0.w + v0.w;
        e1.x = h1.x + v1.x; e1.y = h1.y + v1.y; e1.z = h1.z + v1.z; e1.w = h1.w + v1.w;
        float4* xr2 = (float4*)(out_x2 + (size_t)row * D);
        xr2[tid] = e0;
        xr2[tid + 256] = e1;
    }
}

// ===========================================================================
// Batched weight transpose + tf32 round: Wt[n][k] = tf32(W[k][n]).
// z selects which of 4 weight matrices.
// ===========================================================================
__global__ __launch_bounds__(256) void transpose_round4_kernel(
    const float* __restrict__ W0, const float* __restrict__ W1,
    const float* __restrict__ W2, const float* __restrict__ W3,
    float* __restrict__ T0, float* __restrict__ T1,
    float* __restrict__ T2, float* __restrict__ T3)
{
    __shared__ float t[32][33];
    const float* W = (blockIdx.z == 0) ? W0 : (blockIdx.z == 1) ? W1
                   : (blockIdx.z == 2) ? W2 : W3;
    float* Wt = (blockIdx.z == 0) ? T0 : (blockIdx.z == 1) ? T1
              : (blockIdx.z == 2) ? T2 : T3;
    int bx = blockIdx.x * 32;
    int by = blockIdx.y * 32;
    int tx = threadIdx.x & 31;
    int ty = threadIdx.x >> 5;
    #pragma unroll
    for (int i = 0; i < 4; i++)
        t[ty + i * 8][tx] = W[(size_t)(by + ty + i * 8) * D + bx + tx];
    __syncthreads();
    #pragma unroll
    for (int i = 0; i < 4; i++)
        Wt[(size_t)(bx + ty + i * 8) * D + by + tx] = tf32r(t[tx][ty + i * 8]);
}

// ===========================================================================
// tf32 mma GEMM, CTA 128(M) x 256(N), BK=32, 3-stage cp.async.
// 8 warps in 2(M) x 4(N) grid -> 64x64 warp tiles.
// C[4096, N] = A[4096, 2048] @ Bt[N, 2048]^T  (Bt K-major)
// mode 0: C = tf32(acc) ; mode 1: C = tf32(relu(acc+bias)) ; mode 2: exact+res
// ===========================================================================
#define BM 128
#define BN 256
#define BK 32
#define GSTAGES 3
#define APAD 36
#define A_WORDS (BM * APAD)                  // 4608
#define B_WORDS (BN * APAD)                  // 9216
#define STAGE_WORDS (A_WORDS + B_WORDS)      // 13824
#define STAGE_BYTES (STAGE_WORDS * 4)        // 55296
#define GEMM_SMEM (GSTAGES * STAGE_BYTES)    // 165888

__global__ __launch_bounds__(256, 1) void gemm_tf32_kernel(
    const float* __restrict__ A, const float* __restrict__ Bt,
    float* __restrict__ C, const float* __restrict__ bias,
    const float* __restrict__ res, int N, int mode)
{
    extern __shared__ float smem[];
    const int K = D;
    uint32_t sb = smem_u32(smem);
    int tid = threadIdx.x;
    int wid = tid >> 5;
    int lane = tid & 31;
    int g4 = lane >> 2;
    int t4 = lane & 3;
    int m0 = blockIdx.y * BM;
    int n0 = blockIdx.x * BN;
    int mbase = (wid & 1) * 64;         // 2 M-warps
    int nbase = (wid >> 1) * 64;        // 4 N-warps, 64 cols each

    // ldmatrix per-lane byte offsets (within a stage)
    uint32_t a_off = ((uint32_t)(mbase + (lane & 15)) * APAD + (lane >> 4) * 4) * 4;
    uint32_t b_off = ((uint32_t)A_WORDS
                   + (uint32_t)(nbase + ((lane >> 4) * 8) + (lane & 7)) * APAD
                   + ((lane >> 3) & 1) * 4) * 4;

    float acc[4][8][4];
    #pragma unroll
    for (int mi = 0; mi < 4; mi++)
        #pragma unroll
        for (int ni = 0; ni < 8; ni++)
            #pragma unroll
            for (int r = 0; r < 4; r++) acc[mi][ni][r] = 0.0f;

    const int NCHUNK = K / BK;   // 64

    // 1536 16B-granules per stage: A 1024 rows-chunks? A:128x8=1024, B:256x8=2048
    // total 3072; 256 threads x 12
    auto load_stage = [&](int kc, int st) {
        uint32_t s_a = sb + (uint32_t)st * STAGE_BYTES;
        uint32_t s_b = s_a + A_WORDS * 4;
        #pragma unroll
        for (int i = 0; i < 4; i++) {          // A tile: 1024 granules
            int g = tid + i * 256;
            int r = g >> 3, c = g & 7;
            const float* ga = A + (size_t)(m0 + r) * K + kc * BK + c * 4;
            uint32_t off = (uint32_t)(r * APAD + c * 4) * 4;
            CP_ASYNC16(s_a + off, ga);
        }
        #pragma unroll
        for (int i = 0; i < 8; i++) {          // B tile: 2048 granules
            int g = tid + i * 256;
            int r = g >> 3, c = g & 7;
            const float* gb = Bt + (size_t)(n0 + r) * K + kc * BK + c * 4;
            uint32_t off = (uint32_t)(r * APAD + c * 4) * 4;
            CP_ASYNC16(s_b + off, gb);
        }
    };

    load_stage(0, 0); CP_COMMIT();
    load_stage(1, 1); CP_COMMIT();

    for (int kc = 0; kc < NCHUNK; kc++) {
        int st = kc % GSTAGES;
        CP_WAIT(1);
        __syncthreads();
        if (kc + 2 < NCHUNK) load_stage(kc + 2, (kc + 2) % GSTAGES);
        CP_COMMIT();

        uint32_t stage = sb + (uint32_t)st * STAGE_BYTES;
        #pragma unroll
        for (int s = 0; s < 4; s++) {
            uint32_t a[4][4];
            #pragma unroll
            for (int mi = 0; mi < 4; mi++)
                ldsm_x4(a[mi][0], a[mi][1], a[mi][2], a[mi][3],
                        stage + a_off + (uint32_t)(mi * 16 * APAD + s * 8) * 4);
            uint32_t b[4][4];
            #pragma unroll
            for (int np = 0; np < 4; np++)
                ldsm_x4(b[np][0], b[np][1], b[np][2], b[np][3],
                        stage + b_off + (uint32_t)(np * 16 * APAD + s * 8) * 4);
            #pragma unroll
            for (int mi = 0; mi < 4; mi++)
                #pragma unroll
                for (int ni = 0; ni < 8; ni++)
                    mma_tf32(acc[mi][ni], a[mi][0], a[mi][1], a[mi][2], a[mi][3],
                             b[ni >> 1][(ni & 1) * 2], b[ni >> 1][(ni & 1) * 2 + 1]);
        }
    }

    // ---- epilogue
    #pragma unroll
    for (int mi = 0; mi < 4; mi++) {
        int r0 = m0 + mbase + mi * 16 + g4;
        int r1 = r0 + 8;
        #pragma unroll
        for (int ni = 0; ni < 8; ni++) {
            int c = n0 + nbase + ni * 8 + t4 * 2;
            float v00 = acc[mi][ni][0], v01 = acc[mi][ni][1];
            float v10 = acc[mi][ni][2], v11 = acc[mi][ni][3];
            if (mode >= 1) {
                float b0v = bias[c], b1v = bias[c + 1];
                v00 += b0v; v01 += b1v; v10 += b0v; v11 += b1v;
            }
            if (mode == 1) {
                v00 = tf32r(fmaxf(v00, 0.0f)); v01 = tf32r(fmaxf(v01, 0.0f));
                v10 = tf32r(fmaxf(v10, 0.0f)); v11 = tf32r(fmaxf(v11, 0.0f));
            } else if (mode == 0) {
                v00 = tf32r(v00); v01 = tf32r(v01);
                v10 = tf32r(v10); v11 = tf32r(v11);
            } else {
                const float2* rp0 = (const float2*)(res + (size_t)r0 * N + c);
                const float2* rp1 = (const float2*)(res + (size_t)r1 * N + c);
                float2 rv0 = *rp0, rv1 = *rp1;
                v00 += rv0.x; v01 += rv0.y; v10 += rv1.x; v11 += rv1.y;
            }
            float2 o0; o0.x = v00; o0.y = v01;
            float2 o1; o1.x = v10; o1.y = v11;
            *(float2*)(C + (size_t)r0 * N + c) = o0;
            *(float2*)(C + (size_t)r1 * N + c) = o1;
        }
    }
}

// ===========================================================================
// FUSED attention scores + softmax (unchanged from R4).
// ===========================================================================
#define SC_ROWS 32
#define SC_PAD 68
#define QWORDS (SC_ROWS * SC_PAD)
#define KCH_WORDS (128 * SC_PAD)
#define SC_RED_OFF (QWORDS + 2 * KCH_WORDS)
#define SC_SMEM ((SC_RED_OFF + 256) * 4)

__global__ __launch_bounds__(256, 1) void scores_softmax_kernel(
    const float* __restrict__ qk, float* __restrict__ attn)
{
    extern __shared__ float smem[];
    uint32_t sb = smem_u32(smem);
    int tid = threadIdx.x;
    int wid = tid >> 5;
    int lane = tid & 31;
    int g4 = lane >> 2;
    int t4 = lane & 3;
    int m_warp = wid & 1;
    int n_warp = wid >> 1;
    int mbase = m_warp * 16;

    int ib = blockIdx.x * SC_ROWS;
    int bh = blockIdx.y;
    int b = bh >> 5;
    int h = bh & 31;

    const float* qbase = qk + (size_t)(b * SEQ) * (2 * D) + h * HDIM;
    const float* kbase = qk + (size_t)(b * SEQ) * (2 * D) + D + h * HDIM;

    #pragma unroll
    for (int i = 0; i < 2; i++) {
        int idx = tid + i * 256;
        int r = idx >> 4;
        int c4 = (idx & 15) * 4;
        float4 v = *(const float4*)(qbase + (size_t)(ib + r) * (2 * D) + c4);
        *(float4*)&smem[r * SC_PAD + c4] = v;
    }

    auto load_k = [&](int c) {
        uint32_t kb = sb + (QWORDS + (c & 1) * KCH_WORDS) * 4;
        #pragma unroll
        for (int i = 0; i < 8; i++) {
            int idx = tid + i * 256;
            int r = idx >> 4;
            int c4 = (idx & 15) * 4;
            const float* gp = kbase + (size_t)(c * 128 + r) * (2 * D) + c4;
            CP_ASYNC16(kb + (uint32_t)(r * SC_PAD + c4) * 4, gp);
        }
    };

    load_k(0); CP_COMMIT();
    __syncthreads();

    uint32_t aq_off = ((uint32_t)(mbase + (lane & 15)) * SC_PAD + (lane >> 4) * 4) * 4;
    uint32_t qf[8][4];
    #pragma unroll
    for (int s = 0; s < 8; s++)
        ldsm_x4(qf[s][0], qf[s][1], qf[s][2], qf[s][3], sb + aq_off + (uint32_t)(s * 8) * 4);

    uint32_t bk_off = ((uint32_t)(n_warp * 32 + ((lane >> 4) * 8) + (lane & 7)) * SC_PAD
                     + ((lane >> 3) & 1) * 4) * 4;

    float acc[8][4][4];
    #pragma unroll
    for (int c = 0; c < 8; c++)
        #pragma unroll
        for (int ni = 0; ni < 4; ni++)
            #pragma unroll
            for (int r = 0; r < 4; r++) acc[c][ni][r] = 0.0f;

    #pragma unroll
    for (int c = 0; c < 8; c++) {
        if (c + 1 < 8) { load_k(c + 1); CP_COMMIT(); }
        if (c + 1 < 8) { CP_WAIT(1); } else { CP_WAIT(0); }
        __syncthreads();

        uint32_t kb = sb + (QWORDS + (c & 1) * KCH_WORDS) * 4;
        #pragma unroll
        for (int s = 0; s < 8; s++) {
            uint32_t bk[2][4];
            #pragma unroll
            for (int np = 0; np < 2; np++)
                ldsm_x4(bk[np][0], bk[np][1], bk[np][2], bk[np][3],
                        kb + bk_off + (uint32_t)(np * 16 * SC_PAD + s * 8) * 4);
            #pragma unroll
            for (int ni = 0; ni < 4; ni++)
                mma_tf32(acc[c][ni], qf[s][0], qf[s][1], qf[s][2], qf[s][3],
                         bk[ni >> 1][(ni & 1) * 2], bk[ni >> 1][(ni & 1) * 2 + 1]);
        }
        __syncthreads();
    }

    const float scl = rsqrtf((float)D);
    int row0 = mbase + g4;
    int row1 = row0 + 8;
    float* redm = smem + SC_RED_OFF;
    float* reds = smem + SC_RED_OFF + 128;

    float mx0 = -1e30f, mx1 = -1e30f;
    #pragma unroll
    for (int c = 0; c < 8; c++)
        #pragma unroll
        for (int ni = 0; ni < 4; ni++) {
            mx0 = fmaxf(mx0, fmaxf(acc[c][ni][0], acc[c][ni][1]));
            mx1 = fmaxf(mx1, fmaxf(acc[c][ni][2], acc[c][ni][3]));
        }
    mx0 = fmaxf(mx0, __shfl_xor_sync(0xffffffffu, mx0, 1));
    mx0 = fmaxf(mx0, __shfl_xor_sync(0xffffffffu, mx0, 2));
    mx1 = fmaxf(mx1, __shfl_xor_sync(0xffffffffu, mx1, 1));
    mx1 = fmaxf(mx1, __shfl_xor_sync(0xffffffffu, mx1, 2));
    if (t4 == 0) {
        redm[row0 * 4 + n_warp] = mx0;
        redm[row1 * 4 + n_warp] = mx1;
    }
    __syncthreads();
    mx0 = fmaxf(fmaxf(redm[row0 * 4], redm[row0 * 4 + 1]),
                fmaxf(redm[row0 * 4 + 2], redm[row0 * 4 + 3]));
    mx1 = fmaxf(fmaxf(redm[row1 * 4], redm[row1 * 4 + 1]),
                fmaxf(redm[row1 * 4 + 2], redm[row1 * 4 + 3]));

    float s0 = 0.0f, s1 = 0.0f;
    #pragma unroll
    for (int c = 0; c < 8; c++)
        #pragma unroll
        for (int ni = 0; ni < 4; ni++) {
            float e0 = __expf((acc[c][ni][0] - mx0) * scl);
            float e1 = __expf((acc[c][ni][1] - mx0) * scl);
            float e2 = __expf((acc[c][ni][2] - mx1) * scl);
            float e3 = __expf((acc[c][ni][3] - mx1) * scl);
            acc[c][ni][0] = e0; acc[c][ni][1] = e1;
            acc[c][ni][2] = e2; acc[c][ni][3] = e3;
            s0 += e0 + e1;
            s1 += e2 + e3;
        }
    s0 += __shfl_xor_sync(0xffffffffu, s0, 1);
    s0 += __shfl_xor_sync(0xffffffffu, s0, 2);
    s1 += __shfl_xor_sync(0xffffffffu, s1, 1);
    s1 += __shfl_xor_sync(0xffffffffu, s1, 2);
    if (t4 == 0) {
        reds[row0 * 4 + n_warp] = s0;
        reds[row1 * 4 + n_warp] = s1;
    }
    __syncthreads();
    float inv0 = 1.0f / (reds[row0 * 4] + reds[row0 * 4 + 1]
                       + reds[row0 * 4 + 2] + reds[row0 * 4 + 3]);
    float inv1 = 1.0f / (reds[row1 * 4] + reds[row1 * 4 + 1]
                       + reds[row1 * 4 + 2] + reds[row1 * 4 + 3]);

    float* o0 = attn + (size_t)bh * SEQ * SEQ + (size_t)(ib + row0) * SEQ;
    float* o1 = attn + (size_t)bh * SEQ * SEQ + (size_t)(ib + row1) * SEQ;
    #pragma unroll
    for (int c = 0; c < 8; c++)
        #pragma unroll
        for (int ni = 0; ni < 4; ni++) {
            int col = c * 128 + n_warp * 32 + ni * 8 + t4 * 2;
            float2 p0; p0.x = acc[c][ni][0] * inv0; p0.y = acc[c][ni][1] * inv0;
            float2 p1; p1.x = acc[c][ni][2] * inv1; p1.y = acc[c][ni][3] * inv1;
            *(float2*)(o0 + col) = p0;
            *(float2*)(o1 + col) = p1;
        }
}

// ===========================================================================
// Launch
// ===========================================================================
extern "C" void kernel_launch(void* const* d_in, const int* in_sizes, int n_in,
                              void* d_out, int out_size)
{
    const float* x     = (const float*)d_in[0];
    const float* Wq    = (const float*)d_in[1];
    const float* Wk    = (const float*)d_in[2];
    /* d_in[3] = Wv: DEAD in the reference (attended values are discarded). */
    const float* ln1_s = (const float*)d_in[4];
    const float* ln1_b = (const float*)d_in[5];
    const float* ln2_s = (const float*)d_in[6];
    const float* ln2_b = (const float*)d_in[7];
    const float* ff1_w = (const float*)d_in[8];
    const float* ff1_b = (const float*)d_in[9];
    const float* ff2_w = (const float*)d_in[10];
    const float* ff2_b = (const float*)d_in[11];

    float* out  = (float*)d_out;                       // [4,1024,2048]
    float* attn = out + (size_t)NROWS * D;             // [4,32,1024,1024]

    float *h, *x2, *qk, *h2, *t, *wqkt, *f1t, *f2t;
    cudaGetSymbolAddress((void**)&h,    g_h);
    cudaGetSymbolAddress((void**)&x2,   g_x2);
    cudaGetSymbolAddress((void**)&qk,   g_qk);
    cudaGetSymbolAddress((void**)&h2,   g_h2);
    cudaGetSymbolAddress((void**)&t,    g_t);
    cudaGetSymbolAddress((void**)&wqkt, g_wqkt);
    cudaGetSymbolAddress((void**)&f1t,  g_f1t);
    cudaGetSymbolAddress((void**)&f2t,  g_f2t);

    cudaFuncSetAttribute(gemm_tf32_kernel,
                         cudaFuncAttributeMaxDynamicSharedMemorySize, GEMM_SMEM);
    cudaFuncSetAttribute(scores_softmax_kernel,
                         cudaFuncAttributeMaxDynamicSharedMemorySize, SC_SMEM);

    // Transpose + tf32-round all 4 weights in one launch
    dim3 tg(D / 32, D / 32, 4);
    transpose_round4_kernel<<<tg, 256>>>(Wq, Wk, ff1_w, ff2_w,
                                         wqkt, wqkt + (size_t)D * D, f1t, f2t);

    // LN1
    ln_kernel<<<NROWS, 256>>>(x, ln1_s, ln1_b, h, x2);

    // [q|k] = h @ [Wq|Wk]  (one N=4096 GEMM)
    dim3 gqk(2 * D / BN, NROWS / BM);             // (16, 32)
    gemm_tf32_kernel<<<gqk, 256, GEMM_SMEM>>>(h, wqkt, qk, nullptr, nullptr, 2 * D, 0);

    // fused scores + softmax -> attn
    dim3 gsc(SEQ / SC_ROWS, NBATCH * NHEADS);     // (32, 128)
    scores_softmax_kernel<<<gsc, 256, SC_SMEM>>>(qk, attn);

    // LN2
    ln_kernel<<<NROWS, 256>>>(x2, ln2_s, ln2_b, h2, nullptr);

    // FF
    dim3 gff(D / BN, NROWS / BM);                 // (8, 32)
    gemm_tf32_kernel<<<gff, 256, GEMM_SMEM>>>(h2, f1t, t, ff1_b, nullptr, D, 1);
    gemm_tf32_kernel<<<gff, 256, GEMM_SMEM>>>(t, f2t, out, ff2_b, x2, D, 2);
}

// round 7
// speedup vs baseline: 1.0819x; 1.0819x over previous
#include <cuda_runtime.h>
#include <cstdint>

#define D 2048
#define NROWS 4096     // B*S
#define NHEADS 32
#define HDIM 64
#define SEQ 1024
#define NBATCH 4

// Scratch (allocation-free rule: __device__ globals)
__device__ float g_h  [NROWS * D];       // tf32-rounded LN1 output
__device__ float g_x2 [NROWS * D];       // exact h + x residual
__device__ float g_qk [NROWS * 2 * D];   // tf32-rounded [q | k], row stride 4096
__device__ float g_h2 [NROWS * D];       // tf32-rounded LN2 output
__device__ float g_t  [NROWS * D];       // tf32-rounded relu(ff1)
__device__ float g_wqkt[2 * D * D];      // [Wq^T ; Wk^T] K-major, tf32-rounded
__device__ float g_f1t[D * D];
__device__ float g_f2t[D * D];

// ===========================================================================
// Helpers
// ===========================================================================
__device__ __forceinline__ uint32_t smem_u32(const void* p) {
    uint32_t a;
    asm("{ .reg .u64 t; cvta.to.shared.u64 t, %1; cvt.u32.u64 %0, t; }" : "=r"(a) : "l"(p));
    return a;
}
__device__ __forceinline__ float tf32r(float x) {
    uint32_t u;
    asm("cvt.rna.tf32.f32 %0, %1;" : "=r"(u) : "f"(x));
    return __uint_as_float(u);
}
__device__ __forceinline__ void mma_tf32(float* c, uint32_t a0, uint32_t a1,
                                         uint32_t a2, uint32_t a3,
                                         uint32_t b0, uint32_t b1) {
    asm volatile(
        "mma.sync.aligned.m16n8k8.row.col.f32.tf32.tf32.f32 "
        "{%0,%1,%2,%3}, {%4,%5,%6,%7}, {%8,%9}, {%0,%1,%2,%3};"
        : "+f"(c[0]), "+f"(c[1]), "+f"(c[2]), "+f"(c[3])
        : "r"(a0), "r"(a1), "r"(a2), "r"(a3), "r"(b0), "r"(b1));
}
__device__ __forceinline__ void ldsm_x4(uint32_t& r0, uint32_t& r1,
                                        uint32_t& r2, uint32_t& r3, uint32_t addr) {
    asm volatile("ldmatrix.sync.aligned.m8n8.x4.shared.b16 {%0,%1,%2,%3}, [%4];"
        : "=r"(r0), "=r"(r1), "=r"(r2), "=r"(r3) : "r"(addr));
}
#define CP_ASYNC16(smem_addr, gptr) \
    asm volatile("cp.async.cg.shared.global [%0], [%1], 16;" :: "r"(smem_addr), "l"(gptr) : "memory")
#define CP_COMMIT() asm volatile("cp.async.commit_group;" ::: "memory")
#define CP_WAIT(n)  asm volatile("cp.async.wait_group %0;" :: "n"(n) : "memory")

// ===========================================================================
// Block reductions (256 threads)
// ===========================================================================
__device__ __forceinline__ float blockReduceSum256(float v, float* sh) {
    int tid = threadIdx.x;
    #pragma unroll
    for (int o = 16; o > 0; o >>= 1) v += __shfl_xor_sync(0xffffffffu, v, o);
    if ((tid & 31) == 0) sh[tid >> 5] = v;
    __syncthreads();
    if (tid < 8) {
        float w = sh[tid];
        #pragma unroll
        for (int o = 4; o > 0; o >>= 1) w += __shfl_xor_sync(0xffu, w, o);
        if (tid == 0) sh[0] = w;
    }
    __syncthreads();
    float r = sh[0];
    __syncthreads();
    return r;
}

// ===========================================================================
// LayerNorm
// ===========================================================================
__global__ __launch_bounds__(256) void ln_kernel(
    const float* __restrict__ x, const float* __restrict__ scale,
    const float* __restrict__ bias, float* __restrict__ out_h,
    float* __restrict__ out_x2)
{
    __shared__ float sh[8];
    int row = blockIdx.x;
    int tid = threadIdx.x;
    const float4* xr = (const float4*)(x + (size_t)row * D);
    float4 v0 = xr[tid];
    float4 v1 = xr[tid + 256];
    float s = v0.x + v0.y + v0.z + v0.w + v1.x + v1.y + v1.z + v1.w;
    float mean = blockReduceSum256(s, sh) * (1.0f / (float)D);

    float d0x = v0.x - mean, d0y = v0.y - mean, d0z = v0.z - mean, d0w = v0.w - mean;
    float d1x = v1.x - mean, d1y = v1.y - mean, d1z = v1.z - mean, d1w = v1.w - mean;
    float ss = d0x*d0x + d0y*d0y + d0z*d0z + d0w*d0w
             + d1x*d1x + d1y*d1y + d1z*d1z + d1w*d1w;
    float var = blockReduceSum256(ss, sh) * (1.0f / (float)D);
    float inv = rsqrtf(var + 1e-5f);

    const float4* sc = (const float4*)scale;
    const float4* bi = (const float4*)bias;
    float4 s0 = sc[tid], s1 = sc[tid + 256];
    float4 b0 = bi[tid], b1 = bi[tid + 256];

    float4 h0, h1;
    h0.x = d0x * inv * s0.x + b0.x;  h0.y = d0y * inv * s0.y + b0.y;
    h0.z = d0z * inv * s0.z + b0.z;  h0.w = d0w * inv * s0.w + b0.w;
    h1.x = d1x * inv * s1.x + b1.x;  h1.y = d1y * inv * s1.y + b1.y;
    h1.z = d1z * inv * s1.z + b1.z;  h1.w = d1w * inv * s1.w + b1.w;

    float4 r0, r1;
    r0.x = tf32r(h0.x); r0.y = tf32r(h0.y); r0.z = tf32r(h0.z); r0.w = tf32r(h0.w);
    r1.x = tf32r(h1.x); r1.y = tf32r(h1.y); r1.z = tf32r(h1.z); r1.w = tf32r(h1.w);
    float4* hr = (float4*)(out_h + (size_t)row * D);
    hr[tid] = r0;
    hr[tid + 256] = r1;

    if (out_x2) {
        float4 e0, e1;
        e0.x = h0.x + v0.x; e0.y = h0.y + v0.y; e0.z = h0.z + v0.z; e0.w = h0.w + v0.w;
        e1.x = h1.x + v1.x; e1.y = h1.y + v1.y; e1.z = h1.z + v1.z; e1.w = h1.w + v1.w;
        float4* xr2 = (float4*)(out_x2 + (size_t)row * D);
        xr2[tid] = e0;
        xr2[tid + 256] = e1;
    }
}

// ===========================================================================
// Batched weight transpose + tf32 round: Wt[n][k] = tf32(W[k][n]).
// ===========================================================================
__global__ __launch_bounds__(256) void transpose_round4_kernel(
    const float* __restrict__ W0, const float* __restrict__ W1,
    const float* __restrict__ W2, const float* __restrict__ W3,
    float* __restrict__ T0, float* __restrict__ T1,
    float* __restrict__ T2, float* __restrict__ T3)
{
    __shared__ float t[32][33];
    const float* W = (blockIdx.z == 0) ? W0 : (blockIdx.z == 1) ? W1
                   : (blockIdx.z == 2) ? W2 : W3;
    float* Wt = (blockIdx.z == 0) ? T0 : (blockIdx.z == 1) ? T1
              : (blockIdx.z == 2) ? T2 : T3;
    int bx = blockIdx.x * 32;
    int by = blockIdx.y * 32;
    int tx = threadIdx.x & 31;
    int ty = threadIdx.x >> 5;
    #pragma unroll
    for (int i = 0; i < 4; i++)
        t[ty + i * 8][tx] = W[(size_t)(by + ty + i * 8) * D + bx + tx];
    __syncthreads();
    #pragma unroll
    for (int i = 0; i < 4; i++)
        Wt[(size_t)(bx + ty + i * 8) * D + by + tx] = tf32r(t[tx][ty + i * 8]);
}

// ===========================================================================
// tf32 mma GEMM — R4 configuration (measured best).
// CTA 128x128, BK=32, 3-stage cp.async, 8 warps with 64x32 tiles.
// C[4096, N] = A[4096, 2048] @ Bt[N, 2048]^T  (Bt K-major)
// mode 0: C = tf32(acc) ; mode 1: C = tf32(relu(acc+bias)) ; mode 2: exact+res
// ===========================================================================
#define BM 128
#define BN 128
#define BK 32
#define GSTAGES 3
#define APAD 36
#define TILE_WORDS (128 * APAD)
#define STAGE_WORDS (2 * TILE_WORDS)
#define STAGE_BYTES (STAGE_WORDS * 4)
#define GEMM_SMEM (GSTAGES * STAGE_BYTES)

__global__ __launch_bounds__(256) void gemm_tf32_kernel(
    const float* __restrict__ A, const float* __restrict__ Bt,
    float* __restrict__ C, const float* __restrict__ bias,
    const float* __restrict__ res, int N, int mode)
{
    extern __shared__ float smem[];
    const int K = D;
    uint32_t sb = smem_u32(smem);
    int tid = threadIdx.x;
    int wid = tid >> 5;
    int lane = tid & 31;
    int g4 = lane >> 2;
    int t4 = lane & 3;
    int m0 = blockIdx.y * BM;
    int n0 = blockIdx.x * BN;
    int mbase = (wid & 1) * 64;
    int nbase = (wid >> 1) * 32;

    uint32_t a_off = ((uint32_t)(mbase + (lane & 15)) * APAD + (lane >> 4) * 4) * 4;
    uint32_t b_off = ((uint32_t)TILE_WORDS
                   + (uint32_t)(nbase + ((lane >> 4) * 8) + (lane & 7)) * APAD
                   + ((lane >> 3) & 1) * 4) * 4;

    float acc[4][4][4];
    #pragma unroll
    for (int mi = 0; mi < 4; mi++)
        #pragma unroll
        for (int ni = 0; ni < 4; ni++)
            #pragma unroll
            for (int r = 0; r < 4; r++) acc[mi][ni][r] = 0.0f;

    const int NCHUNK = K / BK;   // 64

    auto load_stage = [&](int kc, int st) {
        uint32_t s_a = sb + (uint32_t)st * STAGE_BYTES;
        uint32_t s_b = s_a + TILE_WORDS * 4;
        #pragma unroll
        for (int i = 0; i < 4; i++) {
            int g = tid + i * 256;
            int r = g >> 3, c = g & 7;
            const float* ga = A  + (size_t)(m0 + r) * K + kc * BK + c * 4;
            const float* gb = Bt + (size_t)(n0 + r) * K + kc * BK + c * 4;
            uint32_t off = (uint32_t)(r * APAD + c * 4) * 4;
            CP_ASYNC16(s_a + off, ga);
            CP_ASYNC16(s_b + off, gb);
        }
    };

    load_stage(0, 0); CP_COMMIT();
    load_stage(1, 1); CP_COMMIT();

    for (int kc = 0; kc < NCHUNK; kc++) {
        int st = kc % GSTAGES;
        CP_WAIT(1);
        __syncthreads();
        if (kc + 2 < NCHUNK) load_stage(kc + 2, (kc + 2) % GSTAGES);
        CP_COMMIT();

        uint32_t stage = sb + (uint32_t)st * STAGE_BYTES;
        #pragma unroll
        for (int s = 0; s < 4; s++) {
            uint32_t a[4][4];
            #pragma unroll
            for (int mi = 0; mi < 4; mi++)
                ldsm_x4(a[mi][0], a[mi][1], a[mi][2], a[mi][3],
                        stage + a_off + (uint32_t)(mi * 16 * APAD + s * 8) * 4);
            uint32_t b[2][4];
            #pragma unroll
            for (int np = 0; np < 2; np++)
                ldsm_x4(b[np][0], b[np][1], b[np][2], b[np][3],
                        stage + b_off + (uint32_t)(np * 16 * APAD + s * 8) * 4);
            #pragma unroll
            for (int mi = 0; mi < 4; mi++)
                #pragma unroll
                for (int ni = 0; ni < 4; ni++)
                    mma_tf32(acc[mi][ni], a[mi][0], a[mi][1], a[mi][2], a[mi][3],
                             b[ni >> 1][(ni & 1) * 2], b[ni >> 1][(ni & 1) * 2 + 1]);
        }
    }

    // ---- epilogue
    #pragma unroll
    for (int mi = 0; mi < 4; mi++) {
        int r0 = m0 + mbase + mi * 16 + g4;
        int r1 = r0 + 8;
        #pragma unroll
        for (int ni = 0; ni < 4; ni++) {
            int c = n0 + nbase + ni * 8 + t4 * 2;
            float v00 = acc[mi][ni][0], v01 = acc[mi][ni][1];
            float v10 = acc[mi][ni][2], v11 = acc[mi][ni][3];
            if (mode >= 1) {
                float b0v = bias[c], b1v = bias[c + 1];
                v00 += b0v; v01 += b1v; v10 += b0v; v11 += b1v;
            }
            if (mode == 1) {
                v00 = tf32r(fmaxf(v00, 0.0f)); v01 = tf32r(fmaxf(v01, 0.0f));
                v10 = tf32r(fmaxf(v10, 0.0f)); v11 = tf32r(fmaxf(v11, 0.0f));
            } else if (mode == 0) {
                v00 = tf32r(v00); v01 = tf32r(v01);
                v10 = tf32r(v10); v11 = tf32r(v11);
            } else {
                const float2* rp0 = (const float2*)(res + (size_t)r0 * N + c);
                const float2* rp1 = (const float2*)(res + (size_t)r1 * N + c);
                float2 rv0 = *rp0, rv1 = *rp1;
                v00 += rv0.x; v01 += rv0.y; v10 += rv1.x; v11 += rv1.y;
            }
            float2 o0; o0.x = v00; o0.y = v01;
            float2 o1; o1.x = v10; o1.y = v11;
            *(float2*)(C + (size_t)r0 * N + c) = o0;
            *(float2*)(C + (size_t)r1 * N + c) = o1;
        }
    }
}

// ===========================================================================
// FUSED attention scores + softmax, with SMEM-staged coalesced output.
// CTA = 32 query rows x 1024 keys for one (b,h). 256 threads.
// After softmax, each 32x128 chunk is staged in smem and written as
// full coalesced float4 rows (512B per warp per row segment).
// ===========================================================================
#define SC_ROWS 32
#define SC_PAD 68
#define QWORDS (SC_ROWS * SC_PAD)            // 2176
#define KCH_WORDS (128 * SC_PAD)             // 8704
#define SC_RED_OFF (QWORDS + 2 * KCH_WORDS)  // 19584 words
#define OPAD 132
#define SC_STAGE_OFF (SC_RED_OFF + 256)      // staging tile [32][OPAD]
#define SC_SMEM ((SC_STAGE_OFF + 32 * OPAD) * 4)

__global__ __launch_bounds__(256, 1) void scores_softmax_kernel(
    const float* __restrict__ qk, float* __restrict__ attn)
{
    extern __shared__ float smem[];
    uint32_t sb = smem_u32(smem);
    int tid = threadIdx.x;
    int wid = tid >> 5;
    int lane = tid & 31;
    int g4 = lane >> 2;
    int t4 = lane & 3;
    int m_warp = wid & 1;
    int n_warp = wid >> 1;
    int mbase = m_warp * 16;

    int ib = blockIdx.x * SC_ROWS;
    int bh = blockIdx.y;
    int b = bh >> 5;
    int h = bh & 31;

    const float* qbase = qk + (size_t)(b * SEQ) * (2 * D) + h * HDIM;
    const float* kbase = qk + (size_t)(b * SEQ) * (2 * D) + D + h * HDIM;

    #pragma unroll
    for (int i = 0; i < 2; i++) {
        int idx = tid + i * 256;
        int r = idx >> 4;
        int c4 = (idx & 15) * 4;
        float4 v = *(const float4*)(qbase + (size_t)(ib + r) * (2 * D) + c4);
        *(float4*)&smem[r * SC_PAD + c4] = v;
    }

    auto load_k = [&](int c) {
        uint32_t kb = sb + (QWORDS + (c & 1) * KCH_WORDS) * 4;
        #pragma unroll
        for (int i = 0; i < 8; i++) {
            int idx = tid + i * 256;
            int r = idx >> 4;
            int c4 = (idx & 15) * 4;
            const float* gp = kbase + (size_t)(c * 128 + r) * (2 * D) + c4;
            CP_ASYNC16(kb + (uint32_t)(r * SC_PAD + c4) * 4, gp);
        }
    };

    load_k(0); CP_COMMIT();
    __syncthreads();

    uint32_t aq_off = ((uint32_t)(mbase + (lane & 15)) * SC_PAD + (lane >> 4) * 4) * 4;
    uint32_t qf[8][4];
    #pragma unroll
    for (int s = 0; s < 8; s++)
        ldsm_x4(qf[s][0], qf[s][1], qf[s][2], qf[s][3], sb + aq_off + (uint32_t)(s * 8) * 4);

    uint32_t bk_off = ((uint32_t)(n_warp * 32 + ((lane >> 4) * 8) + (lane & 7)) * SC_PAD
                     + ((lane >> 3) & 1) * 4) * 4;

    float acc[8][4][4];
    #pragma unroll
    for (int c = 0; c < 8; c++)
        #pragma unroll
        for (int ni = 0; ni < 4; ni++)
            #pragma unroll
            for (int r = 0; r < 4; r++) acc[c][ni][r] = 0.0f;

    #pragma unroll
    for (int c = 0; c < 8; c++) {
        if (c + 1 < 8) { load_k(c + 1); CP_COMMIT(); }
        if (c + 1 < 8) { CP_WAIT(1); } else { CP_WAIT(0); }
        __syncthreads();

        uint32_t kb = sb + (QWORDS + (c & 1) * KCH_WORDS) * 4;
        #pragma unroll
        for (int s = 0; s < 8; s++) {
            uint32_t bk[2][4];
            #pragma unroll
            for (int np = 0; np < 2; np++)
                ldsm_x4(bk[np][0], bk[np][1], bk[np][2], bk[np][3],
                        kb + bk_off + (uint32_t)(np * 16 * SC_PAD + s * 8) * 4);
            #pragma unroll
            for (int ni = 0; ni < 4; ni++)
                mma_tf32(acc[c][ni], qf[s][0], qf[s][1], qf[s][2], qf[s][3],
                         bk[ni >> 1][(ni & 1) * 2], bk[ni >> 1][(ni & 1) * 2 + 1]);
        }
        __syncthreads();
    }

    // ---- softmax factors
    const float scl = rsqrtf((float)D);
    int row0 = mbase + g4;
    int row1 = row0 + 8;
    float* redm = smem + SC_RED_OFF;
    float* reds = smem + SC_RED_OFF + 128;

    float mx0 = -1e30f, mx1 = -1e30f;
    #pragma unroll
    for (int c = 0; c < 8; c++)
        #pragma unroll
        for (int ni = 0; ni < 4; ni++) {
            mx0 = fmaxf(mx0, fmaxf(acc[c][ni][0], acc[c][ni][1]));
            mx1 = fmaxf(mx1, fmaxf(acc[c][ni][2], acc[c][ni][3]));
        }
    mx0 = fmaxf(mx0, __shfl_xor_sync(0xffffffffu, mx0, 1));
    mx0 = fmaxf(mx0, __shfl_xor_sync(0xffffffffu, mx0, 2));
    mx1 = fmaxf(mx1, __shfl_xor_sync(0xffffffffu, mx1, 1));
    mx1 = fmaxf(mx1, __shfl_xor_sync(0xffffffffu, mx1, 2));
    if (t4 == 0) {
        redm[row0 * 4 + n_warp] = mx0;
        redm[row1 * 4 + n_warp] = mx1;
    }
    __syncthreads();
    mx0 = fmaxf(fmaxf(redm[row0 * 4], redm[row0 * 4 + 1]),
                fmaxf(redm[row0 * 4 + 2], redm[row0 * 4 + 3]));
    mx1 = fmaxf(fmaxf(redm[row1 * 4], redm[row1 * 4 + 1]),
                fmaxf(redm[row1 * 4 + 2], redm[row1 * 4 + 3]));

    float s0 = 0.0f, s1 = 0.0f;
    #pragma unroll
    for (int c = 0; c < 8; c++)
        #pragma unroll
        for (int ni = 0; ni < 4; ni++) {
            float e0 = __expf((acc[c][ni][0] - mx0) * scl);
            float e1 = __expf((acc[c][ni][1] - mx0) * scl);
            float e2 = __expf((acc[c][ni][2] - mx1) * scl);
            float e3 = __expf((acc[c][ni][3] - mx1) * scl);
            acc[c][ni][0] = e0; acc[c][ni][1] = e1;
            acc[c][ni][2] = e2; acc[c][ni][3] = e3;
            s0 += e0 + e1;
            s1 += e2 + e3;
        }
    s0 += __shfl_xor_sync(0xffffffffu, s0, 1);
    s0 += __shfl_xor_sync(0xffffffffu, s0, 2);
    s1 += __shfl_xor_sync(0xffffffffu, s1, 1);
    s1 += __shfl_xor_sync(0xffffffffu, s1, 2);
    if (t4 == 0) {
        reds[row0 * 4 + n_warp] = s0;
        reds[row1 * 4 + n_warp] = s1;
    }
    __syncthreads();
    float inv0 = 1.0f / (reds[row0 * 4] + reds[row0 * 4 + 1]
                       + reds[row0 * 4 + 2] + reds[row0 * 4 + 3]);
    float inv1 = 1.0f / (reds[row1 * 4] + reds[row1 * 4 + 1]
                       + reds[row1 * 4 + 2] + reds[row1 * 4 + 3]);

    // ---- write probs: stage 32x128 chunk in smem, then coalesced float4 rows
    float* stage = smem + SC_STAGE_OFF;
    float* obase = attn + (size_t)bh * SEQ * SEQ + (size_t)ib * SEQ;
    #pragma unroll
    for (int c = 0; c < 8; c++) {
        #pragma unroll
        for (int ni = 0; ni < 4; ni++) {
            int col = n_warp * 32 + ni * 8 + t4 * 2;
            float2 p0; p0.x = acc[c][ni][0] * inv0; p0.y = acc[c][ni][1] * inv0;
            float2 p1; p1.x = acc[c][ni][2] * inv1; p1.y = acc[c][ni][3] * inv1;
            *(float2*)&stage[row0 * OPAD + col] = p0;
            *(float2*)&stage[row1 * OPAD + col] = p1;
        }
        __syncthreads();
        #pragma unroll
        for (int i = 0; i < 4; i++) {
            int idx = tid + i * 256;        // 0..1023
            int r = idx >> 5;               // 0..31
            int c4 = (idx & 31) * 4;        // 0..124
            float4 v = *(const float4*)&stage[r * OPAD + c4];
            *(float4*)(obase + (size_t)r * SEQ + c * 128 + c4) = v;
        }
        __syncthreads();
    }
}

// ===========================================================================
// Launch
// ===========================================================================
extern "C" void kernel_launch(void* const* d_in, const int* in_sizes, int n_in,
                              void* d_out, int out_size)
{
    const float* x     = (const float*)d_in[0];
    const float* Wq    = (const float*)d_in[1];
    const float* Wk    = (const float*)d_in[2];
    /* d_in[3] = Wv: DEAD in the reference (attended values are discarded). */
    const float* ln1_s = (const float*)d_in[4];
    const float* ln1_b = (const float*)d_in[5];
    const float* ln2_s = (const float*)d_in[6];
    const float* ln2_b = (const float*)d_in[7];
    const float* ff1_w = (const float*)d_in[8];
    const float* ff1_b = (const float*)d_in[9];
    const float* ff2_w = (const float*)d_in[10];
    const float* ff2_b = (const float*)d_in[11];

    float* out  = (float*)d_out;                       // [4,1024,2048]
    float* attn = out + (size_t)NROWS * D;             // [4,32,1024,1024]

    float *h, *x2, *qk, *h2, *t, *wqkt, *f1t, *f2t;
    cudaGetSymbolAddress((void**)&h,    g_h);
    cudaGetSymbolAddress((void**)&x2,   g_x2);
    cudaGetSymbolAddress((void**)&qk,   g_qk);
    cudaGetSymbolAddress((void**)&h2,   g_h2);
    cudaGetSymbolAddress((void**)&t,    g_t);
    cudaGetSymbolAddress((void**)&wqkt, g_wqkt);
    cudaGetSymbolAddress((void**)&f1t,  g_f1t);
    cudaGetSymbolAddress((void**)&f2t,  g_f2t);

    cudaFuncSetAttribute(gemm_tf32_kernel,
                         cudaFuncAttributeMaxDynamicSharedMemorySize, GEMM_SMEM);
    cudaFuncSetAttribute(scores_softmax_kernel,
                         cudaFuncAttributeMaxDynamicSharedMemorySize, SC_SMEM);

    // Transpose + tf32-round all 4 weights in one launch
    dim3 tg(D / 32, D / 32, 4);
    transpose_round4_kernel<<<tg, 256>>>(Wq, Wk, ff1_w, ff2_w,
                                         wqkt, wqkt + (size_t)D * D, f1t, f2t);

    // LN1
    ln_kernel<<<NROWS, 256>>>(x, ln1_s, ln1_b, h, x2);

    // [q|k] = h @ [Wq|Wk]  (one N=4096 GEMM)
    dim3 gqk(2 * D / BN, NROWS / BM);             // (32, 32)
    gemm_tf32_kernel<<<gqk, 256, GEMM_SMEM>>>(h, wqkt, qk, nullptr, nullptr, 2 * D, 0);

    // fused scores + softmax -> attn
    dim3 gsc(SEQ / SC_ROWS, NBATCH * NHEADS);     // (32, 128)
    scores_softmax_kernel<<<gsc, 256, SC_SMEM>>>(qk, attn);

    // LN2
    ln_kernel<<<NROWS, 256>>>(x2, ln2_s, ln2_b, h2, nullptr);

    // FF
    dim3 gff(D / BN, NROWS / BM);                 // (16, 32)
    gemm_tf32_kernel<<<gff, 256, GEMM_SMEM>>>(h2, f1t, t, ff1_b, nullptr, D, 1);
    gemm_tf32_kernel<<<gff, 256, GEMM_SMEM>>>(t, f2t, out, ff2_b, x2, D, 2);
}

// round 9
// speedup vs baseline: 1.0825x; 1.0005x over previous
#include <cuda_runtime.h>
#include <cstdint>

#define D 2048
#define NROWS 4096     // B*S
#define NHEADS 32
#define HDIM 64
#define SEQ 1024
#define NBATCH 4

// Scratch (allocation-free rule: __device__ globals)
__device__ float g_h  [NROWS * D];       // tf32-rounded LN1 output
__device__ float g_x2 [NROWS * D];       // exact h + x residual
__device__ float g_qk [NROWS * 2 * D];   // tf32-rounded [q | k], row stride 4096
__device__ float g_h2 [NROWS * D];       // tf32-rounded LN2 output
__device__ float g_t  [NROWS * D];       // tf32-rounded relu(ff1)
__device__ float g_wqkt[2 * D * D];      // [Wq^T ; Wk^T] K-major, tf32-rounded
__device__ float g_f1t[D * D];
__device__ float g_f2t[D * D];

// ===========================================================================
// Helpers
// ===========================================================================
__device__ __forceinline__ uint32_t smem_u32(const void* p) {
    uint32_t a;
    asm("{ .reg .u64 t; cvta.to.shared.u64 t, %1; cvt.u32.u64 %0, t; }" : "=r"(a) : "l"(p));
    return a;
}
__device__ __forceinline__ float tf32r(float x) {
    uint32_t u;
    asm("cvt.rna.tf32.f32 %0, %1;" : "=r"(u) : "f"(x));
    return __uint_as_float(u);
}
__device__ __forceinline__ void mma_tf32(float* c, uint32_t a0, uint32_t a1,
                                         uint32_t a2, uint32_t a3,
                                         uint32_t b0, uint32_t b1) {
    asm volatile(
        "mma.sync.aligned.m16n8k8.row.col.f32.tf32.tf32.f32 "
        "{%0,%1,%2,%3}, {%4,%5,%6,%7}, {%8,%9}, {%0,%1,%2,%3};"
        : "+f"(c[0]), "+f"(c[1]), "+f"(c[2]), "+f"(c[3])
        : "r"(a0), "r"(a1), "r"(a2), "r"(a3), "r"(b0), "r"(b1));
}
__device__ __forceinline__ void ldsm_x4(uint32_t& r0, uint32_t& r1,
                                        uint32_t& r2, uint32_t& r3, uint32_t addr) {
    asm volatile("ldmatrix.sync.aligned.m8n8.x4.shared.b16 {%0,%1,%2,%3}, [%4];"
        : "=r"(r0), "=r"(r1), "=r"(r2), "=r"(r3) : "r"(addr));
}
#define CP_ASYNC16(smem_addr, gptr) \
    asm volatile("cp.async.cg.shared.global [%0], [%1], 16;" :: "r"(smem_addr), "l"(gptr) : "memory")
#define CP_COMMIT() asm volatile("cp.async.commit_group;" ::: "memory")
#define CP_WAIT(n)  asm volatile("cp.async.wait_group %0;" :: "n"(n) : "memory")

// ===========================================================================
// Block reductions (256 threads)
// ===========================================================================
__device__ __forceinline__ float blockReduceSum256(float v, float* sh) {
    int tid = threadIdx.x;
    #pragma unroll
    for (int o = 16; o > 0; o >>= 1) v += __shfl_xor_sync(0xffffffffu, v, o);
    if ((tid & 31) == 0) sh[tid >> 5] = v;
    __syncthreads();
    if (tid < 8) {
        float w = sh[tid];
        #pragma unroll
        for (int o = 4; o > 0; o >>= 1) w += __shfl_xor_sync(0xffu, w, o);
        if (tid == 0) sh[0] = w;
    }
    __syncthreads();
    float r = sh[0];
    __syncthreads();
    return r;
}

// ===========================================================================
// LayerNorm
// ===========================================================================
__global__ __launch_bounds__(256) void ln_kernel(
    const float* __restrict__ x, const float* __restrict__ scale,
    const float* __restrict__ bias, float* __restrict__ out_h,
    float* __restrict__ out_x2)
{
    __shared__ float sh[8];
    int row = blockIdx.x;
    int tid = threadIdx.x;
    const float4* xr = (const float4*)(x + (size_t)row * D);
    float4 v0 = xr[tid];
    float4 v1 = xr[tid + 256];
    float s = v0.x + v0.y + v0.z + v0.w + v1.x + v1.y + v1.z + v1.w;
    float mean = blockReduceSum256(s, sh) * (1.0f / (float)D);

    float d0x = v0.x - mean, d0y = v0.y - mean, d0z = v0.z - mean, d0w = v0.w - mean;
    float d1x = v1.x - mean, d1y = v1.y - mean, d1z = v1.z - mean, d1w = v1.w - mean;
    float ss = d0x*d0x + d0y*d0y + d0z*d0z + d0w*d0w
             + d1x*d1x + d1y*d1y + d1z*d1z + d1w*d1w;
    float var = blockReduceSum256(ss, sh) * (1.0f / (float)D);
    float inv = rsqrtf(var + 1e-5f);

    const float4* sc = (const float4*)scale;
    const float4* bi = (const float4*)bias;
    float4 s0 = sc[tid], s1 = sc[tid + 256];
    float4 b0 = bi[tid], b1 = bi[tid + 256];

    float4 h0, h1;
    h0.x = d0x * inv * s0.x + b0.x;  h0.y = d0y * inv * s0.y + b0.y;
    h0.z = d0z * inv * s0.z + b0.z;  h0.w = d0w * inv * s0.w + b0.w;
    h1.x = d1x * inv * s1.x + b1.x;  h1.y = d1y * inv * s1.y + b1.y;
    h1.z = d1z * inv * s1.z + b1.z;  h1.w = d1w * inv * s1.w + b1.w;

    float4 r0, r1;
    r0.x = tf32r(h0.x); r0.y = tf32r(h0.y); r0.z = tf32r(h0.z); r0.w = tf32r(h0.w);
    r1.x = tf32r(h1.x); r1.y = tf32r(h1.y); r1.z = tf32r(h1.z); r1.w = tf32r(h1.w);
    float4* hr = (float4*)(out_h + (size_t)row * D);
    hr[tid] = r0;
    hr[tid + 256] = r1;

    if (out_x2) {
        float4 e0, e1;
        e0.x = h0.x + v0.x; e0.y = h0.y + v0.y; e0.z = h0.z + v0.z; e0.w = h0.w + v0.w;
        e1.x = h1.x + v1.x; e1.y = h1.y + v1.y; e1.z = h1.z + v1.z; e1.w = h1.w + v1.w;
        float4* xr2 = (float4*)(out_x2 + (size_t)row * D);
        xr2[tid] = e0;
        xr2[tid + 256] = e1;
    }
}

// ===========================================================================
// Batched weight transpose + tf32 round: Wt[n][k] = tf32(W[k][n]).
// ===========================================================================
__global__ __launch_bounds__(256) void transpose_round4_kernel(
    const float* __restrict__ W0, const float* __restrict__ W1,
    const float* __restrict__ W2, const float* __restrict__ W3,
    float* __restrict__ T0, float* __restrict__ T1,
    float* __restrict__ T2, float* __restrict__ T3)
{
    __shared__ float t[32][33];
    const float* W = (blockIdx.z == 0) ? W0 : (blockIdx.z == 1) ? W1
                   : (blockIdx.z == 2) ? W2 : W3;
    float* Wt = (blockIdx.z == 0) ? T0 : (blockIdx.z == 1) ? T1
              : (blockIdx.z == 2) ? T2 : T3;
    int bx = blockIdx.x * 32;
    int by = blockIdx.y * 32;
    int tx = threadIdx.x & 31;
    int ty = threadIdx.x >> 5;
    #pragma unroll
    for (int i = 0; i < 4; i++)
        t[ty + i * 8][tx] = W[(size_t)(by + ty + i * 8) * D + bx + tx];
    __syncthreads();
    #pragma unroll
    for (int i = 0; i < 4; i++)
        Wt[(size_t)(bx + ty + i * 8) * D + by + tx] = tf32r(t[tx][ty + i * 8]);
}

// ===========================================================================
// tf32 mma GEMM — R4 shape, now capped to 2 CTAs/SM.
// CTA 128x128, BK=32, 3-stage cp.async, 8 warps with 64x32 tiles.
// C[4096, N] = A[4096, 2048] @ Bt[N, 2048]^T  (Bt K-major)
// mode 0: C = tf32(acc) ; mode 1: C = tf32(relu(acc+bias)) ; mode 2: exact+res
// ===========================================================================
#define BM 128
#define BN 128
#define BK 32
#define GSTAGES 3
#define APAD 36
#define TILE_WORDS (128 * APAD)
#define STAGE_WORDS (2 * TILE_WORDS)
#define STAGE_BYTES (STAGE_WORDS * 4)
#define GEMM_SMEM (GSTAGES * STAGE_BYTES)    // 110592 B -> 2 CTAs = 221184 fits

__global__ __launch_bounds__(256, 2) void gemm_tf32_kernel(
    const float* __restrict__ A, const float* __restrict__ Bt,
    float* __restrict__ C, const float* __restrict__ bias,
    const float* __restrict__ res, int N, int mode)
{
    extern __shared__ float smem[];
    const int K = D;
    uint32_t sb = smem_u32(smem);
    int tid = threadIdx.x;
    int wid = tid >> 5;
    int lane = tid & 31;
    int g4 = lane >> 2;
    int t4 = lane & 3;
    int m0 = blockIdx.y * BM;
    int n0 = blockIdx.x * BN;
    int mbase = (wid & 1) * 64;
    int nbase = (wid >> 1) * 32;

    uint32_t a_off = ((uint32_t)(mbase + (lane & 15)) * APAD + (lane >> 4) * 4) * 4;
    uint32_t b_off = ((uint32_t)TILE_WORDS
                   + (uint32_t)(nbase + ((lane >> 4) * 8) + (lane & 7)) * APAD
                   + ((lane >> 3) & 1) * 4) * 4;

    float acc[4][4][4];
    #pragma unroll
    for (int mi = 0; mi < 4; mi++)
        #pragma unroll
        for (int ni = 0; ni < 4; ni++)
            #pragma unroll
            for (int r = 0; r < 4; r++) acc[mi][ni][r] = 0.0f;

    const int NCHUNK = K / BK;   // 64

    auto load_stage = [&](int kc, int st) {
        uint32_t s_a = sb + (uint32_t)st * STAGE_BYTES;
        uint32_t s_b = s_a + TILE_WORDS * 4;
        #pragma unroll
        for (int i = 0; i < 4; i++) {
            int g = tid + i * 256;
            int r = g >> 3, c = g & 7;
            const float* ga = A  + (size_t)(m0 + r) * K + kc * BK + c * 4;
            const float* gb = Bt + (size_t)(n0 + r) * K + kc * BK + c * 4;
            uint32_t off = (uint32_t)(r * APAD + c * 4) * 4;
            CP_ASYNC16(s_a + off, ga);
            CP_ASYNC16(s_b + off, gb);
        }
    };

    load_stage(0, 0); CP_COMMIT();
    load_stage(1, 1); CP_COMMIT();

    for (int kc = 0; kc < NCHUNK; kc++) {
        int st = kc % GSTAGES;
        CP_WAIT(1);
        __syncthreads();
        if (kc + 2 < NCHUNK) load_stage(kc + 2, (kc + 2) % GSTAGES);
        CP_COMMIT();

        uint32_t stage = sb + (uint32_t)st * STAGE_BYTES;
        #pragma unroll
        for (int s = 0; s < 4; s++) {
            uint32_t a[4][4];
            #pragma unroll
            for (int mi = 0; mi < 4; mi++)
                ldsm_x4(a[mi][0], a[mi][1], a[mi][2], a[mi][3],
                        stage + a_off + (uint32_t)(mi * 16 * APAD + s * 8) * 4);
            uint32_t b[2][4];
            #pragma unroll
            for (int np = 0; np < 2; np++)
                ldsm_x4(b[np][0], b[np][1], b[np][2], b[np][3],
                        stage + b_off + (uint32_t)(np * 16 * APAD + s * 8) * 4);
            #pragma unroll
            for (int mi = 0; mi < 4; mi++)
                #pragma unroll
                for (int ni = 0; ni < 4; ni++)
                    mma_tf32(acc[mi][ni], a[mi][0], a[mi][1], a[mi][2], a[mi][3],
                             b[ni >> 1][(ni & 1) * 2], b[ni >> 1][(ni & 1) * 2 + 1]);
        }
    }

    // ---- epilogue
    #pragma unroll
    for (int mi = 0; mi < 4; mi++) {
        int r0 = m0 + mbase + mi * 16 + g4;
        int r1 = r0 + 8;
        #pragma unroll
        for (int ni = 0; ni < 4; ni++) {
            int c = n0 + nbase + ni * 8 + t4 * 2;
            float v00 = acc[mi][ni][0], v01 = acc[mi][ni][1];
            float v10 = acc[mi][ni][2], v11 = acc[mi][ni][3];
            if (mode >= 1) {
                float b0v = bias[c], b1v = bias[c + 1];
                v00 += b0v; v01 += b1v; v10 += b0v; v11 += b1v;
            }
            if (mode == 1) {
                v00 = tf32r(fmaxf(v00, 0.0f)); v01 = tf32r(fmaxf(v01, 0.0f));
                v10 = tf32r(fmaxf(v10, 0.0f)); v11 = tf32r(fmaxf(v11, 0.0f));
            } else if (mode == 0) {
                v00 = tf32r(v00); v01 = tf32r(v01);
                v10 = tf32r(v10); v11 = tf32r(v11);
            } else {
                const float2* rp0 = (const float2*)(res + (size_t)r0 * N + c);
                const float2* rp1 = (const float2*)(res + (size_t)r1 * N + c);
                float2 rv0 = *rp0, rv1 = *rp1;
                v00 += rv0.x; v01 += rv0.y; v10 += rv1.x; v11 += rv1.y;
            }
            float2 o0; o0.x = v00; o0.y = v01;
            float2 o1; o1.x = v10; o1.y = v11;
            *(float2*)(C + (size_t)r0 * N + c) = o0;
            *(float2*)(C + (size_t)r1 * N + c) = o1;
        }
    }
}

// ===========================================================================
// FUSED attention scores + softmax — 16 Q-rows per CTA, 2 CTAs/SM.
// 256 threads, 8 warps: all share the single 16-row M tile; warp w owns
// 16 key-columns (w*16) of each 128-key chunk. K streamed in 8 chunks
// (double-buffered cp.async). Full score row in registers (64/thread).
// ===========================================================================
#define SC_ROWS 16
#define SC_PAD 68
#define QWORDS (SC_ROWS * SC_PAD)            // 1088
#define KCH_WORDS (128 * SC_PAD)             // 8704
#define SC_RED_OFF (QWORDS + 2 * KCH_WORDS)  // 18496 words
#define SC_SMEM ((SC_RED_OFF + 256) * 4)     // 75008 B -> 2 CTAs = 150016 fits

__global__ __launch_bounds__(256, 2) void scores_softmax_kernel(
    const float* __restrict__ qk, float* __restrict__ attn)
{
    extern __shared__ float smem[];
    uint32_t sb = smem_u32(smem);
    int tid = threadIdx.x;
    int wid = tid >> 5;        // n_warp 0..7
    int lane = tid & 31;
    int g4 = lane >> 2;
    int t4 = lane & 3;

    int ib = blockIdx.x * SC_ROWS;
    int bh = blockIdx.y;
    int b = bh >> 5;
    int h = bh & 31;

    const float* qbase = qk + (size_t)(b * SEQ) * (2 * D) + h * HDIM;
    const float* kbase = qk + (size_t)(b * SEQ) * (2 * D) + D + h * HDIM;

    // ---- load Q tile (16 x 64): 256 float4 granules, 1 per thread
    {
        int r = tid >> 4;
        int c4 = (tid & 15) * 4;
        float4 v = *(const float4*)(qbase + (size_t)(ib + r) * (2 * D) + c4);
        *(float4*)&smem[r * SC_PAD + c4] = v;
    }

    auto load_k = [&](int c) {
        uint32_t kb = sb + (QWORDS + (c & 1) * KCH_WORDS) * 4;
        #pragma unroll
        for (int i = 0; i < 8; i++) {
            int idx = tid + i * 256;
            int r = idx >> 4;
            int c4 = (idx & 15) * 4;
            const float* gp = kbase + (size_t)(c * 128 + r) * (2 * D) + c4;
            CP_ASYNC16(kb + (uint32_t)(r * SC_PAD + c4) * 4, gp);
        }
    };

    load_k(0); CP_COMMIT();
    __syncthreads();   // Q tile visible

    // ---- preload Q fragments (8 k-steps, m16k8 each)
    uint32_t aq_off = ((uint32_t)(lane & 15) * SC_PAD + (lane >> 4) * 4) * 4;
    uint32_t qf[8][4];
    #pragma unroll
    for (int s = 0; s < 8; s++)
        ldsm_x4(qf[s][0], qf[s][1], qf[s][2], qf[s][3], sb + aq_off + (uint32_t)(s * 8) * 4);

    // B-frag: n16 x k8 per ldsm_x4; warp w covers keys w*16..w*16+15 of chunk
    uint32_t bk_off = ((uint32_t)(wid * 16 + ((lane >> 4) * 8) + (lane & 7)) * SC_PAD
                     + ((lane >> 3) & 1) * 4) * 4;

    float acc[8][2][4];
    #pragma unroll
    for (int c = 0; c < 8; c++)
        #pragma unroll
        for (int ni = 0; ni < 2; ni++)
            #pragma unroll
            for (int r = 0; r < 4; r++) acc[c][ni][r] = 0.0f;

    #pragma unroll
    for (int c = 0; c < 8; c++) {
        if (c + 1 < 8) { load_k(c + 1); CP_COMMIT(); }
        if (c + 1 < 8) { CP_WAIT(1); } else { CP_WAIT(0); }
        __syncthreads();

        uint32_t kb = sb + (QWORDS + (c & 1) * KCH_WORDS) * 4;
        #pragma unroll
        for (int s = 0; s < 8; s++) {
            uint32_t bk[4];
            ldsm_x4(bk[0], bk[1], bk[2], bk[3],
                    kb + bk_off + (uint32_t)(s * 8) * 4);
            mma_tf32(acc[c][0], qf[s][0], qf[s][1], qf[s][2], qf[s][3], bk[0], bk[1]);
            mma_tf32(acc[c][1], qf[s][0], qf[s][1], qf[s][2], qf[s][3], bk[2], bk[3]);
        }
        __syncthreads();
    }

    // ---- softmax over the full row (1024 values spread across 8 warps)
    const float scl = rsqrtf((float)D);
    int row0 = g4;            // local 0..7
    int row1 = g4 + 8;        // local 8..15
    float* redm = smem + SC_RED_OFF;        // [16][8]
    float* reds = smem + SC_RED_OFF + 128;  // [16][8]

    float mx0 = -1e30f, mx1 = -1e30f;
    #pragma unroll
    for (int c = 0; c < 8; c++)
        #pragma unroll
        for (int ni = 0; ni < 2; ni++) {
            mx0 = fmaxf(mx0, fmaxf(acc[c][ni][0], acc[c][ni][1]));
            mx1 = fmaxf(mx1, fmaxf(acc[c][ni][2], acc[c][ni][3]));
        }
    mx0 = fmaxf(mx0, __shfl_xor_sync(0xffffffffu, mx0, 1));
    mx0 = fmaxf(mx0, __shfl_xor_sync(0xffffffffu, mx0, 2));
    mx1 = fmaxf(mx1, __shfl_xor_sync(0xffffffffu, mx1, 1));
    mx1 = fmaxf(mx1, __shfl_xor_sync(0xffffffffu, mx1, 2));
    if (t4 == 0) {
        redm[row0 * 8 + wid] = mx0;
        redm[row1 * 8 + wid] = mx1;
    }
    __syncthreads();
    mx0 = redm[row0 * 8];
    mx1 = redm[row1 * 8];
    #pragma unroll
    for (int w = 1; w < 8; w++) {
        mx0 = fmaxf(mx0, redm[row0 * 8 + w]);
        mx1 = fmaxf(mx1, redm[row1 * 8 + w]);
    }

    float s0 = 0.0f, s1 = 0.0f;
    #pragma unroll
    for (int c = 0; c < 8; c++)
        #pragma unroll
        for (int ni = 0; ni < 2; ni++) {
            float e0 = __expf((acc[c][ni][0] - mx0) * scl);
            float e1 = __expf((acc[c][ni][1] - mx0) * scl);
            float e2 = __expf((acc[c][ni][2] - mx1) * scl);
            float e3 = __expf((acc[c][ni][3] - mx1) * scl);
            acc[c][ni][0] = e0; acc[c][ni][1] = e1;
            acc[c][ni][2] = e2; acc[c][ni][3] = e3;
            s0 += e0 + e1;
            s1 += e2 + e3;
        }
    s0 += __shfl_xor_sync(0xffffffffu, s0, 1);
    s0 += __shfl_xor_sync(0xffffffffu, s0, 2);
    s1 += __shfl_xor_sync(0xffffffffu, s1, 1);
    s1 += __shfl_xor_sync(0xffffffffu, s1, 2);
    if (t4 == 0) {
        reds[row0 * 8 + wid] = s0;
        reds[row1 * 8 + wid] = s1;
    }
    __syncthreads();
    float t0 = 0.0f, t1 = 0.0f;
    #pragma unroll
    for (int w = 0; w < 8; w++) {
        t0 += reds[row0 * 8 + w];
        t1 += reds[row1 * 8 + w];
    }
    float inv0 = 1.0f / t0;
    float inv1 = 1.0f / t1;

    // ---- write probs
    float* o0 = attn + (size_t)bh * SEQ * SEQ + (size_t)(ib + row0) * SEQ;
    float* o1 = attn + (size_t)bh * SEQ * SEQ + (size_t)(ib + row1) * SEQ;
    #pragma unroll
    for (int c = 0; c < 8; c++)
        #pragma unroll
        for (int ni = 0; ni < 2; ni++) {
            int col = c * 128 + wid * 16 + ni * 8 + t4 * 2;
            float2 p0; p0.x = acc[c][ni][0] * inv0; p0.y = acc[c][ni][1] * inv0;
            float2 p1; p1.x = acc[c][ni][2] * inv1; p1.y = acc[c][ni][3] * inv1;
            *(float2*)(o0 + col) = p0;
            *(float2*)(o1 + col) = p1;
        }
}

// ===========================================================================
// Launch
// ===========================================================================
extern "C" void kernel_launch(void* const* d_in, const int* in_sizes, int n_in,
                              void* d_out, int out_size)
{
    const float* x     = (const float*)d_in[0];
    const float* Wq    = (const float*)d_in[1];
    const float* Wk    = (const float*)d_in[2];
    /* d_in[3] = Wv: DEAD in the reference (attended values are discarded). */
    const float* ln1_s = (const float*)d_in[4];
    const float* ln1_b = (const float*)d_in[5];
    const float* ln2_s = (const float*)d_in[6];
    const float* ln2_b = (const float*)d_in[7];
    const float* ff1_w = (const float*)d_in[8];
    const float* ff1_b = (const float*)d_in[9];
    const float* ff2_w = (const float*)d_in[10];
    const float* ff2_b = (const float*)d_in[11];

    float* out  = (float*)d_out;                       // [4,1024,2048]
    float* attn = out + (size_t)NROWS * D;             // [4,32,1024,1024]

    float *h, *x2, *qk, *h2, *t, *wqkt, *f1t, *f2t;
    cudaGetSymbolAddress((void**)&h,    g_h);
    cudaGetSymbolAddress((void**)&x2,   g_x2);
    cudaGetSymbolAddress((void**)&qk,   g_qk);
    cudaGetSymbolAddress((void**)&h2,   g_h2);
    cudaGetSymbolAddress((void**)&t,    g_t);
    cudaGetSymbolAddress((void**)&wqkt, g_wqkt);
    cudaGetSymbolAddress((void**)&f1t,  g_f1t);
    cudaGetSymbolAddress((void**)&f2t,  g_f2t);

    cudaFuncSetAttribute(gemm_tf32_kernel,
                         cudaFuncAttributeMaxDynamicSharedMemorySize, GEMM_SMEM);
    cudaFuncSetAttribute(scores_softmax_kernel,
                         cudaFuncAttributeMaxDynamicSharedMemorySize, SC_SMEM);

    // Transpose + tf32-round all 4 weights in one launch
    dim3 tg(D / 32, D / 32, 4);
    transpose_round4_kernel<<<tg, 256>>>(Wq, Wk, ff1_w, ff2_w,
                                         wqkt, wqkt + (size_t)D * D, f1t, f2t);

    // LN1
    ln_kernel<<<NROWS, 256>>>(x, ln1_s, ln1_b, h, x2);

    // [q|k] = h @ [Wq|Wk]  (one N=4096 GEMM)
    dim3 gqk(2 * D / BN, NROWS / BM);             // (32, 32)
    gemm_tf32_kernel<<<gqk, 256, GEMM_SMEM>>>(h, wqkt, qk, nullptr, nullptr, 2 * D, 0);

    // fused scores + softmax -> attn
    dim3 gsc(SEQ / SC_ROWS, NBATCH * NHEADS);     // (64, 128)
    scores_softmax_kernel<<<gsc, 256, SC_SMEM>>>(qk, attn);

    // LN2
    ln_kernel<<<NROWS, 256>>>(x2, ln2_s, ln2_b, h2, nullptr);

    // FF
    dim3 gff(D / BN, NROWS / BM);                 // (16, 32)
    gemm_tf32_kernel<<<gff, 256, GEMM_SMEM>>>(h2, f1t, t, ff1_b, nullptr, D, 1);
    gemm_tf32_kernel<<<gff, 256, GEMM_SMEM>>>(t, f2t, out, ff2_b, x2, D, 2);
}

// round 10
// speedup vs baseline: 1.0832x; 1.0007x over previous
#include <cuda_runtime.h>
#include <cstdint>

#define D 2048
#define NROWS 4096     // B*S
#define NHEADS 32
#define HDIM 64
#define SEQ 1024
#define NBATCH 4

// Scratch (allocation-free rule: __device__ globals)
__device__ float g_h  [NROWS * D];       // tf32-rounded LN1 output
__device__ float g_x2 [NROWS * D];       // exact h + x residual
__device__ float g_qk [NROWS * 2 * D];   // tf32-rounded [q | k], row stride 4096
__device__ float g_h2 [NROWS * D];       // tf32-rounded LN2 output
__device__ float g_t  [NROWS * D];       // tf32-rounded relu(ff1)
__device__ float g_wqkt[2 * D * D];      // [Wq^T ; Wk^T] K-major, tf32-rounded
__device__ float g_f1t[D * D];
__device__ float g_f2t[D * D];

// ===========================================================================
// Helpers
// ===========================================================================
__device__ __forceinline__ uint32_t smem_u32(const void* p) {
    uint32_t a;
    asm("{ .reg .u64 t; cvta.to.shared.u64 t, %1; cvt.u32.u64 %0, t; }" : "=r"(a) : "l"(p));
    return a;
}
__device__ __forceinline__ float tf32r(float x) {
    uint32_t u;
    asm("cvt.rna.tf32.f32 %0, %1;" : "=r"(u) : "f"(x));
    return __uint_as_float(u);
}
__device__ __forceinline__ void mma_tf32(float* c, uint32_t a0, uint32_t a1,
                                         uint32_t a2, uint32_t a3,
                                         uint32_t b0, uint32_t b1) {
    asm volatile(
        "mma.sync.aligned.m16n8k8.row.col.f32.tf32.tf32.f32 "
        "{%0,%1,%2,%3}, {%4,%5,%6,%7}, {%8,%9}, {%0,%1,%2,%3};"
        : "+f"(c[0]), "+f"(c[1]), "+f"(c[2]), "+f"(c[3])
        : "r"(a0), "r"(a1), "r"(a2), "r"(a3), "r"(b0), "r"(b1));
}
__device__ __forceinline__ void ldsm_x4(uint32_t& r0, uint32_t& r1,
                                        uint32_t& r2, uint32_t& r3, uint32_t addr) {
    asm volatile("ldmatrix.sync.aligned.m8n8.x4.shared.b16 {%0,%1,%2,%3}, [%4];"
        : "=r"(r0), "=r"(r1), "=r"(r2), "=r"(r3) : "r"(addr));
}
#define CP_ASYNC16(smem_addr, gptr) \
    asm volatile("cp.async.cg.shared.global [%0], [%1], 16;" :: "r"(smem_addr), "l"(gptr) : "memory")
#define CP_COMMIT() asm volatile("cp.async.commit_group;" ::: "memory")
#define CP_WAIT(n)  asm volatile("cp.async.wait_group %0;" :: "n"(n) : "memory")

// ===========================================================================
// Block reductions (256 threads)
// ===========================================================================
__device__ __forceinline__ float blockReduceSum256(float v, float* sh) {
    int tid = threadIdx.x;
    #pragma unroll
    for (int o = 16; o > 0; o >>= 1) v += __shfl_xor_sync(0xffffffffu, v, o);
    if ((tid & 31) == 0) sh[tid >> 5] = v;
    __syncthreads();
    if (tid < 8) {
        float w = sh[tid];
        #pragma unroll
        for (int o = 4; o > 0; o >>= 1) w += __shfl_xor_sync(0xffu, w, o);
        if (tid == 0) sh[0] = w;
    }
    __syncthreads();
    float r = sh[0];
    __syncthreads();
    return r;
}

// ===========================================================================
// LayerNorm
// ===========================================================================
__global__ __launch_bounds__(256) void ln_kernel(
    const float* __restrict__ x, const float* __restrict__ scale,
    const float* __restrict__ bias, float* __restrict__ out_h,
    float* __restrict__ out_x2)
{
    __shared__ float sh[8];
    int row = blockIdx.x;
    int tid = threadIdx.x;
    const float4* xr = (const float4*)(x + (size_t)row * D);
    float4 v0 = xr[tid];
    float4 v1 = xr[tid + 256];
    float s = v0.x + v0.y + v0.z + v0.w + v1.x + v1.y + v1.z + v1.w;
    float mean = blockReduceSum256(s, sh) * (1.0f / (float)D);

    float d0x = v0.x - mean, d0y = v0.y - mean, d0z = v0.z - mean, d0w = v0.w - mean;
    float d1x = v1.x - mean, d1y = v1.y - mean, d1z = v1.z - mean, d1w = v1.w - mean;
    float ss = d0x*d0x + d0y*d0y + d0z*d0z + d0w*d0w
             + d1x*d1x + d1y*d1y + d1z*d1z + d1w*d1w;
    float var = blockReduceSum256(ss, sh) * (1.0f / (float)D);
    float inv = rsqrtf(var + 1e-5f);

    const float4* sc = (const float4*)scale;
    const float4* bi = (const float4*)bias;
    float4 s0 = sc[tid], s1 = sc[tid + 256];
    float4 b0 = bi[tid], b1 = bi[tid + 256];

    float4 h0, h1;
    h0.x = d0x * inv * s0.x + b0.x;  h0.y = d0y * inv * s0.y + b0.y;
    h0.z = d0z * inv * s0.z + b0.z;  h0.w = d0w * inv * s0.w + b0.w;
    h1.x = d1x * inv * s1.x + b1.x;  h1.y = d1y * inv * s1.y + b1.y;
    h1.z = d1z * inv * s1.z + b1.z;  h1.w = d1w * inv * s1.w + b1.w;

    float4 r0, r1;
    r0.x = tf32r(h0.x); r0.y = tf32r(h0.y); r0.z = tf32r(h0.z); r0.w = tf32r(h0.w);
    r1.x = tf32r(h1.x); r1.y = tf32r(h1.y); r1.z = tf32r(h1.z); r1.w = tf32r(h1.w);
    float4* hr = (float4*)(out_h + (size_t)row * D);
    hr[tid] = r0;
    hr[tid + 256] = r1;

    if (out_x2) {
        float4 e0, e1;
        e0.x = h0.x + v0.x; e0.y = h0.y + v0.y; e0.z = h0.z + v0.z; e0.w = h0.w + v0.w;
        e1.x = h1.x + v1.x; e1.y = h1.y + v1.y; e1.z = h1.z + v1.z; e1.w = h1.w + v1.w;
        float4* xr2 = (float4*)(out_x2 + (size_t)row * D);
        xr2[tid] = e0;
        xr2[tid + 256] = e1;
    }
}

// ===========================================================================
// Batched weight transpose + tf32 round: Wt[n][k] = tf32(W[k][n]).
// ===========================================================================
__global__ __launch_bounds__(256) void transpose_round4_kernel(
    const float* __restrict__ W0, const float* __restrict__ W1,
    const float* __restrict__ W2, const float* __restrict__ W3,
    float* __restrict__ T0, float* __restrict__ T1,
    float* __restrict__ T2, float* __restrict__ T3)
{
    __shared__ float t[32][33];
    const float* W = (blockIdx.z == 0) ? W0 : (blockIdx.z == 1) ? W1
                   : (blockIdx.z == 2) ? W2 : W3;
    float* Wt = (blockIdx.z == 0) ? T0 : (blockIdx.z == 1) ? T1
              : (blockIdx.z == 2) ? T2 : T3;
    int bx = blockIdx.x * 32;
    int by = blockIdx.y * 32;
    int tx = threadIdx.x & 31;
    int ty = threadIdx.x >> 5;
    #pragma unroll
    for (int i = 0; i < 4; i++)
        t[ty + i * 8][tx] = W[(size_t)(by + ty + i * 8) * D + bx + tx];
    __syncthreads();
    #pragma unroll
    for (int i = 0; i < 4; i++)
        Wt[(size_t)(bx + ty + i * 8) * D + by + tx] = tf32r(t[tx][ty + i * 8]);
}

// ===========================================================================
// tf32 mma GEMM — R4 shape, now capped to 2 CTAs/SM.
// CTA 128x128, BK=32, 3-stage cp.async, 8 warps with 64x32 tiles.
// C[4096, N] = A[4096, 2048] @ Bt[N, 2048]^T  (Bt K-major)
// mode 0: C = tf32(acc) ; mode 1: C = tf32(relu(acc+bias)) ; mode 2: exact+res
// ===========================================================================
#define BM 128
#define BN 128
#define BK 32
#define GSTAGES 3
#define APAD 36
#define TILE_WORDS (128 * APAD)
#define STAGE_WORDS (2 * TILE_WORDS)
#define STAGE_BYTES (STAGE_WORDS * 4)
#define GEMM_SMEM (GSTAGES * STAGE_BYTES)    // 110592 B -> 2 CTAs = 221184 fits

__global__ __launch_bounds__(256, 2) void gemm_tf32_kernel(
    const float* __restrict__ A, const float* __restrict__ Bt,
    float* __restrict__ C, const float* __restrict__ bias,
    const float* __restrict__ res, int N, int mode)
{
    extern __shared__ float smem[];
    const int K = D;
    uint32_t sb = smem_u32(smem);
    int tid = threadIdx.x;
    int wid = tid >> 5;
    int lane = tid & 31;
    int g4 = lane >> 2;
    int t4 = lane & 3;
    int m0 = blockIdx.y * BM;
    int n0 = blockIdx.x * BN;
    int mbase = (wid & 1) * 64;
    int nbase = (wid >> 1) * 32;

    uint32_t a_off = ((uint32_t)(mbase + (lane & 15)) * APAD + (lane >> 4) * 4) * 4;
    uint32_t b_off = ((uint32_t)TILE_WORDS
                   + (uint32_t)(nbase + ((lane >> 4) * 8) + (lane & 7)) * APAD
                   + ((lane >> 3) & 1) * 4) * 4;

    float acc[4][4][4];
    #pragma unroll
    for (int mi = 0; mi < 4; mi++)
        #pragma unroll
        for (int ni = 0; ni < 4; ni++)
            #pragma unroll
            for (int r = 0; r < 4; r++) acc[mi][ni][r] = 0.0f;

    const int NCHUNK = K / BK;   // 64

    auto load_stage = [&](int kc, int st) {
        uint32_t s_a = sb + (uint32_t)st * STAGE_BYTES;
        uint32_t s_b = s_a + TILE_WORDS * 4;
        #pragma unroll
        for (int i = 0; i < 4; i++) {
            int g = tid + i * 256;
            int r = g >> 3, c = g & 7;
            const float* ga = A  + (size_t)(m0 + r) * K + kc * BK + c * 4;
            const float* gb = Bt + (size_t)(n0 + r) * K + kc * BK + c * 4;
            uint32_t off = (uint32_t)(r * APAD + c * 4) * 4;
            CP_ASYNC16(s_a + off, ga);
            CP_ASYNC16(s_b + off, gb);
        }
    };

    load_stage(0, 0); CP_COMMIT();
    load_stage(1, 1); CP_COMMIT();

    for (int kc = 0; kc < NCHUNK; kc++) {
        int st = kc % GSTAGES;
        CP_WAIT(1);
        __syncthreads();
        if (kc + 2 < NCHUNK) load_stage(kc + 2, (kc + 2) % GSTAGES);
        CP_COMMIT();

        uint32_t stage = sb + (uint32_t)st * STAGE_BYTES;
        #pragma unroll
        for (int s = 0; s < 4; s++) {
            uint32_t a[4][4];
            #pragma unroll
            for (int mi = 0; mi < 4; mi++)
                ldsm_x4(a[mi][0], a[mi][1], a[mi][2], a[mi][3],
                        stage + a_off + (uint32_t)(mi * 16 * APAD + s * 8) * 4);
            uint32_t b[2][4];
            #pragma unroll
            for (int np = 0; np < 2; np++)
                ldsm_x4(b[np][0], b[np][1], b[np][2], b[np][3],
                        stage + b_off + (uint32_t)(np * 16 * APAD + s * 8) * 4);
            #pragma unroll
            for (int mi = 0; mi < 4; mi++)
                #pragma unroll
                for (int ni = 0; ni < 4; ni++)
                    mma_tf32(acc[mi][ni], a[mi][0], a[mi][1], a[mi][2], a[mi][3],
                             b[ni >> 1][(ni & 1) * 2], b[ni >> 1][(ni & 1) * 2 + 1]);
        }
    }

    // ---- epilogue
    #pragma unroll
    for (int mi = 0; mi < 4; mi++) {
        int r0 = m0 + mbase + mi * 16 + g4;
        int r1 = r0 + 8;
        #pragma unroll
        for (int ni = 0; ni < 4; ni++) {
            int c = n0 + nbase + ni * 8 + t4 * 2;
            float v00 = acc[mi][ni][0], v01 = acc[mi][ni][1];
            float v10 = acc[mi][ni][2], v11 = acc[mi][ni][3];
            if (mode >= 1) {
                float b0v = bias[c], b1v = bias[c + 1];
                v00 += b0v; v01 += b1v; v10 += b0v; v11 += b1v;
            }
            if (mode == 1) {
                v00 = tf32r(fmaxf(v00, 0.0f)); v01 = tf32r(fmaxf(v01, 0.0f));
                v10 = tf32r(fmaxf(v10, 0.0f)); v11 = tf32r(fmaxf(v11, 0.0f));
            } else if (mode == 0) {
                v00 = tf32r(v00); v01 = tf32r(v01);
                v10 = tf32r(v10); v11 = tf32r(v11);
            } else {
                const float2* rp0 = (const float2*)(res + (size_t)r0 * N + c);
                const float2* rp1 = (const float2*)(res + (size_t)r1 * N + c);
                float2 rv0 = *rp0, rv1 = *rp1;
                v00 += rv0.x; v01 += rv0.y; v10 += rv1.x; v11 += rv1.y;
            }
            float2 o0; o0.x = v00; o0.y = v01;
            float2 o1; o1.x = v10; o1.y = v11;
            *(float2*)(C + (size_t)r0 * N + c) = o0;
            *(float2*)(C + (size_t)r1 * N + c) = o1;
        }
    }
}

// ===========================================================================
// FUSED attention scores + softmax — 16 Q-rows per CTA, 2 CTAs/SM.
// 256 threads, 8 warps: all share the single 16-row M tile; warp w owns
// 16 key-columns (w*16) of each 128-key chunk. K streamed in 8 chunks
// (double-buffered cp.async). Full score row in registers (64/thread).
// ===========================================================================
#define SC_ROWS 16
#define SC_PAD 68
#define QWORDS (SC_ROWS * SC_PAD)            // 1088
#define KCH_WORDS (128 * SC_PAD)             // 8704
#define SC_RED_OFF (QWORDS + 2 * KCH_WORDS)  // 18496 words
#define SC_SMEM ((SC_RED_OFF + 256) * 4)     // 75008 B -> 2 CTAs = 150016 fits

__global__ __launch_bounds__(256, 2) void scores_softmax_kernel(
    const float* __restrict__ qk, float* __restrict__ attn)
{
    extern __shared__ float smem[];
    uint32_t sb = smem_u32(smem);
    int tid = threadIdx.x;
    int wid = tid >> 5;        // n_warp 0..7
    int lane = tid & 31;
    int g4 = lane >> 2;
    int t4 = lane & 3;

    int ib = blockIdx.x * SC_ROWS;
    int bh = blockIdx.y;
    int b = bh >> 5;
    int h = bh & 31;

    const float* qbase = qk + (size_t)(b * SEQ) * (2 * D) + h * HDIM;
    const float* kbase = qk + (size_t)(b * SEQ) * (2 * D) + D + h * HDIM;

    // ---- load Q tile (16 x 64): 256 float4 granules, 1 per thread
    {
        int r = tid >> 4;
        int c4 = (tid & 15) * 4;
        float4 v = *(const float4*)(qbase + (size_t)(ib + r) * (2 * D) + c4);
        *(float4*)&smem[r * SC_PAD + c4] = v;
    }

    auto load_k = [&](int c) {
        uint32_t kb = sb + (QWORDS + (c & 1) * KCH_WORDS) * 4;
        #pragma unroll
        for (int i = 0; i < 8; i++) {
            int idx = tid + i * 256;
            int r = idx >> 4;
            int c4 = (idx & 15) * 4;
            const float* gp = kbase + (size_t)(c * 128 + r) * (2 * D) + c4;
            CP_ASYNC16(kb + (uint32_t)(r * SC_PAD + c4) * 4, gp);
        }
    };

    load_k(0); CP_COMMIT();
    __syncthreads();   // Q tile visible

    // ---- preload Q fragments (8 k-steps, m16k8 each)
    uint32_t aq_off = ((uint32_t)(lane & 15) * SC_PAD + (lane >> 4) * 4) * 4;
    uint32_t qf[8][4];
    #pragma unroll
    for (int s = 0; s < 8; s++)
        ldsm_x4(qf[s][0], qf[s][1], qf[s][2], qf[s][3], sb + aq_off + (uint32_t)(s * 8) * 4);

    // B-frag: n16 x k8 per ldsm_x4; warp w covers keys w*16..w*16+15 of chunk
    uint32_t bk_off = ((uint32_t)(wid * 16 + ((lane >> 4) * 8) + (lane & 7)) * SC_PAD
                     + ((lane >> 3) & 1) * 4) * 4;

    float acc[8][2][4];
    #pragma unroll
    for (int c = 0; c < 8; c++)
        #pragma unroll
        for (int ni = 0; ni < 2; ni++)
            #pragma unroll
            for (int r = 0; r < 4; r++) acc[c][ni][r] = 0.0f;

    #pragma unroll
    for (int c = 0; c < 8; c++) {
        if (c + 1 < 8) { load_k(c + 1); CP_COMMIT(); }
        if (c + 1 < 8) { CP_WAIT(1); } else { CP_WAIT(0); }
        __syncthreads();

        uint32_t kb = sb + (QWORDS + (c & 1) * KCH_WORDS) * 4;
        #pragma unroll
        for (int s = 0; s < 8; s++) {
            uint32_t bk[4];
            ldsm_x4(bk[0], bk[1], bk[2], bk[3],
                    kb + bk_off + (uint32_t)(s * 8) * 4);
            mma_tf32(acc[c][0], qf[s][0], qf[s][1], qf[s][2], qf[s][3], bk[0], bk[1]);
            mma_tf32(acc[c][1], qf[s][0], qf[s][1], qf[s][2], qf[s][3], bk[2], bk[3]);
        }
        __syncthreads();
    }

    // ---- softmax over the full row (1024 values spread across 8 warps)
    const float scl = rsqrtf((float)D);
    int row0 = g4;            // local 0..7
    int row1 = g4 + 8;        // local 8..15
    float* redm = smem + SC_RED_OFF;        // [16][8]
    float* reds = smem + SC_RED_OFF + 128;  // [16][8]

    float mx0 = -1e30f, mx1 = -1e30f;
    #pragma unroll
    for (int c = 0; c < 8; c++)
        #pragma unroll
        for (int ni = 0; ni < 2; ni++) {
            mx0 = fmaxf(mx0, fmaxf(acc[c][ni][0], acc[c][ni][1]));
            mx1 = fmaxf(mx1, fmaxf(acc[c][ni][2], acc[c][ni][3]));
        }
    mx0 = fmaxf(mx0, __shfl_xor_sync(0xffffffffu, mx0, 1));
    mx0 = fmaxf(mx0, __shfl_xor_sync(0xffffffffu, mx0, 2));
    mx1 = fmaxf(mx1, __shfl_xor_sync(0xffffffffu, mx1, 1));
    mx1 = fmaxf(mx1, __shfl_xor_sync(0xffffffffu, mx1, 2));
    if (t4 == 0) {
        redm[row0 * 8 + wid] = mx0;
        redm[row1 * 8 + wid] = mx1;
    }
    __syncthreads();
    mx0 = redm[row0 * 8];
    mx1 = redm[row1 * 8];
    #pragma unroll
    for (int w = 1; w < 8; w++) {
        mx0 = fmaxf(mx0, redm[row0 * 8 + w]);
        mx1 = fmaxf(mx1, redm[row1 * 8 + w]);
    }

    float s0 = 0.0f, s1 = 0.0f;
    #pragma unroll
    for (int c = 0; c < 8; c++)
        #pragma unroll
        for (int ni = 0; ni < 2; ni++) {
            float e0 = __expf((acc[c][ni][0] - mx0) * scl);
            float e1 = __expf((acc[c][ni][1] - mx0) * scl);
            float e2 = __expf((acc[c][ni][2] - mx1) * scl);
            float e3 = __expf((acc[c][ni][3] - mx1) * scl);
            acc[c][ni][0] = e0; acc[c][ni][1] = e1;
            acc[c][ni][2] = e2; acc[c][ni][3] = e3;
            s0 += e0 + e1;
            s1 += e2 + e3;
        }
    s0 += __shfl_xor_sync(0xffffffffu, s0, 1);
    s0 += __shfl_xor_sync(0xffffffffu, s0, 2);
    s1 += __shfl_xor_sync(0xffffffffu, s1, 1);
    s1 += __shfl_xor_sync(0xffffffffu, s1, 2);
    if (t4 == 0) {
        reds[row0 * 8 + wid] = s0;
        reds[row1 * 8 + wid] = s1;
    }
    __syncthreads();
    float t0 = 0.0f, t1 = 0.0f;
    #pragma unroll
    for (int w = 0; w < 8; w++) {
        t0 += reds[row0 * 8 + w];
        t1 += reds[row1 * 8 + w];
    }
    float inv0 = 1.0f / t0;
    float inv1 = 1.0f / t1;

    // ---- write probs
    float* o0 = attn + (size_t)bh * SEQ * SEQ + (size_t)(ib + row0) * SEQ;
    float* o1 = attn + (size_t)bh * SEQ * SEQ + (size_t)(ib + row1) * SEQ;
    #pragma unroll
    for (int c = 0; c < 8; c++)
        #pragma unroll
        for (int ni = 0; ni < 2; ni++) {
            int col = c * 128 + wid * 16 + ni * 8 + t4 * 2;
            float2 p0; p0.x = acc[c][ni][0] * inv0; p0.y = acc[c][ni][1] * inv0;
            float2 p1; p1.x = acc[c][ni][2] * inv1; p1.y = acc[c][ni][3] * inv1;
            *(float2*)(o0 + col) = p0;
            *(float2*)(o1 + col) = p1;
        }
}

// ===========================================================================
// Launch
// ===========================================================================
extern "C" void kernel_launch(void* const* d_in, const int* in_sizes, int n_in,
                              void* d_out, int out_size)
{
    const float* x     = (const float*)d_in[0];
    const float* Wq    = (const float*)d_in[1];
    const float* Wk    = (const float*)d_in[2];
    /* d_in[3] = Wv: DEAD in the reference (attended values are discarded). */
    const float* ln1_s = (const float*)d_in[4];
    const float* ln1_b = (const float*)d_in[5];
    const float* ln2_s = (const float*)d_in[6];
    const float* ln2_b = (const float*)d_in[7];
    const float* ff1_w = (const float*)d_in[8];
    const float* ff1_b = (const float*)d_in[9];
    const float* ff2_w = (const float*)d_in[10];
    const float* ff2_b = (const float*)d_in[11];

    float* out  = (float*)d_out;                       // [4,1024,2048]
    float* attn = out + (size_t)NROWS * D;             // [4,32,1024,1024]

    float *h, *x2, *qk, *h2, *t, *wqkt, *f1t, *f2t;
    cudaGetSymbolAddress((void**)&h,    g_h);
    cudaGetSymbolAddress((void**)&x2,   g_x2);
    cudaGetSymbolAddress((void**)&qk,   g_qk);
    cudaGetSymbolAddress((void**)&h2,   g_h2);
    cudaGetSymbolAddress((void**)&t,    g_t);
    cudaGetSymbolAddress((void**)&wqkt, g_wqkt);
    cudaGetSymbolAddress((void**)&f1t,  g_f1t);
    cudaGetSymbolAddress((void**)&f2t,  g_f2t);

    cudaFuncSetAttribute(gemm_tf32_kernel,
                         cudaFuncAttributeMaxDynamicSharedMemorySize, GEMM_SMEM);
    cudaFuncSetAttribute(scores_softmax_kernel,
                         cudaFuncAttributeMaxDynamicSharedMemorySize, SC_SMEM);

    // Transpose + tf32-round all 4 weights in one launch
    dim3 tg(D / 32, D / 32, 4);
    transpose_round4_kernel<<<tg, 256>>>(Wq, Wk, ff1_w, ff2_w,
                                         wqkt, wqkt + (size_t)D * D, f1t, f2t);

    // LN1
    ln_kernel<<<NROWS, 256>>>(x, ln1_s, ln1_b, h, x2);

    // [q|k] = h @ [Wq|Wk]  (one N=4096 GEMM)
    dim3 gqk(2 * D / BN, NROWS / BM);             // (32, 32)
    gemm_tf32_kernel<<<gqk, 256, GEMM_SMEM>>>(h, wqkt, qk, nullptr, nullptr, 2 * D, 0);

    // fused scores + softmax -> attn
    dim3 gsc(SEQ / SC_ROWS, NBATCH * NHEADS);     // (64, 128)
    scores_softmax_kernel<<<gsc, 256, SC_SMEM>>>(qk, attn);

    // LN2
    ln_kernel<<<NROWS, 256>>>(x2, ln2_s, ln2_b, h2, nullptr);

    // FF
    dim3 gff(D / BN, NROWS / BM);                 // (16, 32)
    gemm_tf32_kernel<<<gff, 256, GEMM_SMEM>>>(h2, f1t, t, ff1_b, nullptr, D, 1);
    gemm_tf32_kernel<<<gff, 256, GEMM_SMEM>>>(t, f2t, out, ff2_b, x2, D, 2);
}

// round 14
// speedup vs baseline: 1.0979x; 1.0136x over previous
#include <cuda_runtime.h>
#include <cstdint>

#define D 2048
#define NROWS 4096     // B*S
#define NHEADS 32
#define HDIM 64
#define SEQ 1024
#define NBATCH 4

// Scratch (allocation-free rule: __device__ globals)
__device__ float g_h  [NROWS * D];       // tf32-rounded LN1 output
__device__ float g_x2 [NROWS * D];       // exact h + x residual
__device__ float g_qk [NROWS * 2 * D];   // tf32-rounded [q | k], row stride 4096
__device__ float g_h2 [NROWS * D];       // tf32-rounded LN2 output
__device__ float g_t  [NROWS * D];       // tf32-rounded relu(ff1)
__device__ float g_wqkt[2 * D * D];      // [Wq^T ; Wk^T] K-major, tf32-rounded
__device__ float g_f1t[D * D];
__device__ float g_f2t[D * D];

// ===========================================================================
// Helpers
// ===========================================================================
__device__ __forceinline__ uint32_t smem_u32(const void* p) {
    uint32_t a;
    asm("{ .reg .u64 t; cvta.to.shared.u64 t, %1; cvt.u32.u64 %0, t; }" : "=r"(a) : "l"(p));
    return a;
}
__device__ __forceinline__ float tf32r(float x) {
    uint32_t u;
    asm("cvt.rna.tf32.f32 %0, %1;" : "=r"(u) : "f"(x));
    return __uint_as_float(u);
}
__device__ __forceinline__ void mma_tf32(float* c, uint32_t a0, uint32_t a1,
                                         uint32_t a2, uint32_t a3,
                                         uint32_t b0, uint32_t b1) {
    asm volatile(
        "mma.sync.aligned.m16n8k8.row.col.f32.tf32.tf32.f32 "
        "{%0,%1,%2,%3}, {%4,%5,%6,%7}, {%8,%9}, {%0,%1,%2,%3};"
        : "+f"(c[0]), "+f"(c[1]), "+f"(c[2]), "+f"(c[3])
        : "r"(a0), "r"(a1), "r"(a2), "r"(a3), "r"(b0), "r"(b1));
}
__device__ __forceinline__ void ldsm_x4(uint32_t& r0, uint32_t& r1,
                                        uint32_t& r2, uint32_t& r3, uint32_t addr) {
    asm volatile("ldmatrix.sync.aligned.m8n8.x4.shared.b16 {%0,%1,%2,%3}, [%4];"
        : "=r"(r0), "=r"(r1), "=r"(r2), "=r"(r3) : "r"(addr));
}
#define CP_ASYNC16(smem_addr, gptr) \
    asm volatile("cp.async.cg.shared.global [%0], [%1], 16;" :: "r"(smem_addr), "l"(gptr) : "memory")
#define CP_COMMIT() asm volatile("cp.async.commit_group;" ::: "memory")
#define CP_WAIT(n)  asm volatile("cp.async.wait_group %0;" :: "n"(n) : "memory")

// ===========================================================================
// Block reductions (256 threads)
// ===========================================================================
__device__ __forceinline__ float blockReduceSum256(float v, float* sh) {
    int tid = threadIdx.x;
    #pragma unroll
    for (int o = 16; o > 0; o >>= 1) v += __shfl_xor_sync(0xffffffffu, v, o);
    if ((tid & 31) == 0) sh[tid >> 5] = v;
    __syncthreads();
    if (tid < 8) {
        float w = sh[tid];
        #pragma unroll
        for (int o = 4; o > 0; o >>= 1) w += __shfl_xor_sync(0xffu, w, o);
        if (tid == 0) sh[0] = w;
    }
    __syncthreads();
    float r = sh[0];
    __syncthreads();
    return r;
}

// ===========================================================================
// LayerNorm
// ===========================================================================
__global__ __launch_bounds__(256) void ln_kernel(
    const float* __restrict__ x, const float* __restrict__ scale,
    const float* __restrict__ bias, float* __restrict__ out_h,
    float* __restrict__ out_x2)
{
    __shared__ float sh[8];
    int row = blockIdx.x;
    int tid = threadIdx.x;
    const float4* xr = (const float4*)(x + (size_t)row * D);
    float4 v0 = xr[tid];
    float4 v1 = xr[tid + 256];
    float s = v0.x + v0.y + v0.z + v0.w + v1.x + v1.y + v1.z + v1.w;
    float mean = blockReduceSum256(s, sh) * (1.0f / (float)D);

    float d0x = v0.x - mean, d0y = v0.y - mean, d0z = v0.z - mean, d0w = v0.w - mean;
    float d1x = v1.x - mean, d1y = v1.y - mean, d1z = v1.z - mean, d1w = v1.w - mean;
    float ss = d0x*d0x + d0y*d0y + d0z*d0z + d0w*d0w
             + d1x*d1x + d1y*d1y + d1z*d1z + d1w*d1w;
    float var = blockReduceSum256(ss, sh) * (1.0f / (float)D);
    float inv = rsqrtf(var + 1e-5f);

    const float4* sc = (const float4*)scale;
    const float4* bi = (const float4*)bias;
    float4 s0 = sc[tid], s1 = sc[tid + 256];
    float4 b0 = bi[tid], b1 = bi[tid + 256];

    float4 h0, h1;
    h0.x = d0x * inv * s0.x + b0.x;  h0.y = d0y * inv * s0.y + b0.y;
    h0.z = d0z * inv * s0.z + b0.z;  h0.w = d0w * inv * s0.w + b0.w;
    h1.x = d1x * inv * s1.x + b1.x;  h1.y = d1y * inv * s1.y + b1.y;
    h1.z = d1z * inv * s1.z + b1.z;  h1.w = d1w * inv * s1.w + b1.w;

    float4 r0, r1;
    r0.x = tf32r(h0.x); r0.y = tf32r(h0.y); r0.z = tf32r(h0.z); r0.w = tf32r(h0.w);
    r1.x = tf32r(h1.x); r1.y = tf32r(h1.y); r1.z = tf32r(h1.z); r1.w = tf32r(h1.w);
    float4* hr = (float4*)(out_h + (size_t)row * D);
    hr[tid] = r0;
    hr[tid + 256] = r1;

    if (out_x2) {
        float4 e0, e1;
        e0.x = h0.x + v0.x; e0.y = h0.y + v0.y; e0.z = h0.z + v0.z; e0.w = h0.w + v0.w;
        e1.x = h1.x + v1.x; e1.y = h1.y + v1.y; e1.z = h1.z + v1.z; e1.w = h1.w + v1.w;
        float4* xr2 = (float4*)(out_x2 + (size_t)row * D);
        xr2[tid] = e0;
        xr2[tid + 256] = e1;
    }
}

// ===========================================================================
// Batched weight transpose + tf32 round: Wt[n][k] = tf32(W[k][n]).
// ===========================================================================
__global__ __launch_bounds__(256) void transpose_round4_kernel(
    const float* __restrict__ W0, const float* __restrict__ W1,
    const float* __restrict__ W2, const float* __restrict__ W3,
    float* __restrict__ T0, float* __restrict__ T1,
    float* __restrict__ T2, float* __restrict__ T3)
{
    __shared__ float t[32][33];
    const float* W = (blockIdx.z == 0) ? W0 : (blockIdx.z == 1) ? W1
                   : (blockIdx.z == 2) ? W2 : W3;
    float* Wt = (blockIdx.z == 0) ? T0 : (blockIdx.z == 1) ? T1
              : (blockIdx.z == 2) ? T2 : T3;
    int bx = blockIdx.x * 32;
    int by = blockIdx.y * 32;
    int tx = threadIdx.x & 31;
    int ty = threadIdx.x >> 5;
    #pragma unroll
    for (int i = 0; i < 4; i++)
        t[ty + i * 8][tx] = W[(size_t)(by + ty + i * 8) * D + bx + tx];
    __syncthreads();
    #pragma unroll
    for (int i = 0; i < 4; i++)
        Wt[(size_t)(bx + ty + i * 8) * D + by + tx] = tf32r(t[tx][ty + i * 8]);
}

// ===========================================================================
// tf32 mma GEMM — measured-best configuration (R4 shape, 2 CTAs/SM).
// CTA 128x128, BK=32, 3-stage cp.async, 8 warps with 64x32 tiles.
// mode 0: C = tf32(acc) ; mode 1: C = tf32(relu(acc+bias)) ; mode 2: exact+res
// ===========================================================================
#define BM 128
#define BN 128
#define BK 32
#define GSTAGES 3
#define APAD 36
#define TILE_WORDS (128 * APAD)
#define STAGE_WORDS (2 * TILE_WORDS)
#define STAGE_BYTES (STAGE_WORDS * 4)
#define GEMM_SMEM (GSTAGES * STAGE_BYTES)

__global__ __launch_bounds__(256, 2) void gemm_tf32_kernel(
    const float* __restrict__ A, const float* __restrict__ Bt,
    float* __restrict__ C, const float* __restrict__ bias,
    const float* __restrict__ res, int N, int mode)
{
    extern __shared__ float smem[];
    const int K = D;
    uint32_t sb = smem_u32(smem);
    int tid = threadIdx.x;
    int wid = tid >> 5;
    int lane = tid & 31;
    int g4 = lane >> 2;
    int t4 = lane & 3;
    int m0 = blockIdx.y * BM;
    int n0 = blockIdx.x * BN;
    int mbase = (wid & 1) * 64;
    int nbase = (wid >> 1) * 32;

    uint32_t a_off = ((uint32_t)(mbase + (lane & 15)) * APAD + (lane >> 4) * 4) * 4;
    uint32_t b_off = ((uint32_t)TILE_WORDS
                   + (uint32_t)(nbase + ((lane >> 4) * 8) + (lane & 7)) * APAD
                   + ((lane >> 3) & 1) * 4) * 4;

    float acc[4][4][4];
    #pragma unroll
    for (int mi = 0; mi < 4; mi++)
        #pragma unroll
        for (int ni = 0; ni < 4; ni++)
            #pragma unroll
            for (int r = 0; r < 4; r++) acc[mi][ni][r] = 0.0f;

    const int NCHUNK = K / BK;   // 64

    auto load_stage = [&](int kc, int st) {
        uint32_t s_a = sb + (uint32_t)st * STAGE_BYTES;
        uint32_t s_b = s_a + TILE_WORDS * 4;
        #pragma unroll
        for (int i = 0; i < 4; i++) {
            int g = tid + i * 256;
            int r = g >> 3, c = g & 7;
            const float* ga = A  + (size_t)(m0 + r) * K + kc * BK + c * 4;
            const float* gb = Bt + (size_t)(n0 + r) * K + kc * BK + c * 4;
            uint32_t off = (uint32_t)(r * APAD + c * 4) * 4;
            CP_ASYNC16(s_a + off, ga);
            CP_ASYNC16(s_b + off, gb);
        }
    };

    load_stage(0, 0); CP_COMMIT();
    load_stage(1, 1); CP_COMMIT();

    for (int kc = 0; kc < NCHUNK; kc++) {
        int st = kc % GSTAGES;
        CP_WAIT(1);
        __syncthreads();
        if (kc + 2 < NCHUNK) load_stage(kc + 2, (kc + 2) % GSTAGES);
        CP_COMMIT();

        uint32_t stage = sb + (uint32_t)st * STAGE_BYTES;
        #pragma unroll
        for (int s = 0; s < 4; s++) {
            uint32_t a[4][4];
            #pragma unroll
            for (int mi = 0; mi < 4; mi++)
                ldsm_x4(a[mi][0], a[mi][1], a[mi][2], a[mi][3],
                        stage + a_off + (uint32_t)(mi * 16 * APAD + s * 8) * 4);
            uint32_t b[2][4];
            #pragma unroll
            for (int np = 0; np < 2; np++)
                ldsm_x4(b[np][0], b[np][1], b[np][2], b[np][3],
                        stage + b_off + (uint32_t)(np * 16 * APAD + s * 8) * 4);
            #pragma unroll
            for (int mi = 0; mi < 4; mi++)
                #pragma unroll
                for (int ni = 0; ni < 4; ni++)
                    mma_tf32(acc[mi][ni], a[mi][0], a[mi][1], a[mi][2], a[mi][3],
                             b[ni >> 1][(ni & 1) * 2], b[ni >> 1][(ni & 1) * 2 + 1]);
        }
    }

    // ---- epilogue
    #pragma unroll
    for (int mi = 0; mi < 4; mi++) {
        int r0 = m0 + mbase + mi * 16 + g4;
        int r1 = r0 + 8;
        #pragma unroll
        for (int ni = 0; ni < 4; ni++) {
            int c = n0 + nbase + ni * 8 + t4 * 2;
            float v00 = acc[mi][ni][0], v01 = acc[mi][ni][1];
            float v10 = acc[mi][ni][2], v11 = acc[mi][ni][3];
            if (mode >= 1) {
                float b0v = bias[c], b1v = bias[c + 1];
                v00 += b0v; v01 += b1v; v10 += b0v; v11 += b1v;
            }
            if (mode == 1) {
                v00 = tf32r(fmaxf(v00, 0.0f)); v01 = tf32r(fmaxf(v01, 0.0f));
                v10 = tf32r(fmaxf(v10, 0.0f)); v11 = tf32r(fmaxf(v11, 0.0f));
            } else if (mode == 0) {
                v00 = tf32r(v00); v01 = tf32r(v01);
                v10 = tf32r(v10); v11 = tf32r(v11);
            } else {
                const float2* rp0 = (const float2*)(res + (size_t)r0 * N + c);
                const float2* rp1 = (const float2*)(res + (size_t)r1 * N + c);
                float2 rv0 = *rp0, rv1 = *rp1;
                v00 += rv0.x; v01 += rv0.y; v10 += rv1.x; v11 += rv1.y;
            }
            float2 o0; o0.x = v00; o0.y = v01;
            float2 o1; o1.x = v10; o1.y = v11;
            *(float2*)(C + (size_t)r0 * N + c) = o0;
            *(float2*)(C + (size_t)r1 * N + c) = o1;
        }
    }
}

// ===========================================================================
// TWO-PASS fused scores + softmax.
// CTA = 64 Q-rows x 1024 keys for one (b,h); 8 warps = 4(M) x 2(N);
// warp tile per 128-key chunk: 16 rows x 64 keys -> 8 independent mma chains.
// Pass 1: stream K chunks, online (max,sum) per row only (32 acc regs).
// Pass 2: re-stream K, recompute scores, normalize, store immediately.
// 2 CTAs/SM (regs ~120, smem 88KB).
// ===========================================================================
#define SC_ROWS 64
#define SC_PAD 68
#define QWORDS (SC_ROWS * SC_PAD)            // 4352
#define KCH_WORDS (128 * SC_PAD)             // 8704
#define SC_RED_OFF (QWORDS + 2 * KCH_WORDS)  // 21760 words
#define SC_SMEM ((SC_RED_OFF + 256) * 4)     // 88064 B -> 2 CTAs fits

__global__ __launch_bounds__(256, 2) void scores_softmax_kernel(
    const float* __restrict__ qk, float* __restrict__ attn)
{
    extern __shared__ float smem[];
    uint32_t sb = smem_u32(smem);
    int tid = threadIdx.x;
    int wid = tid >> 5;
    int lane = tid & 31;
    int g4 = lane >> 2;
    int t4 = lane & 3;
    int m_warp = wid & 3;        // 4 M-warps, 16 rows each
    int n_warp = wid >> 2;       // 2 N-warps, 64 keys each per chunk
    int mbase = m_warp * 16;

    int ib = blockIdx.x * SC_ROWS;
    int bh = blockIdx.y;
    int b = bh >> 5;
    int h = bh & 31;

    const float* qbase = qk + (size_t)(b * SEQ) * (2 * D) + h * HDIM;
    const float* kbase = qk + (size_t)(b * SEQ) * (2 * D) + D + h * HDIM;

    // ---- load Q tile (64 x 64): 1024 float4 granules
    #pragma unroll
    for (int i = 0; i < 4; i++) {
        int idx = tid + i * 256;
        int r = idx >> 4;
        int c4 = (idx & 15) * 4;
        float4 v = *(const float4*)(qbase + (size_t)(ib + r) * (2 * D) + c4);
        *(float4*)&smem[r * SC_PAD + c4] = v;
    }

    auto load_k = [&](int c) {
        uint32_t kb = sb + (QWORDS + (c & 1) * KCH_WORDS) * 4;
        #pragma unroll
        for (int i = 0; i < 8; i++) {
            int idx = tid + i * 256;
            int r = idx >> 4;
            int c4 = (idx & 15) * 4;
            const float* gp = kbase + (size_t)(c * 128 + r) * (2 * D) + c4;
            CP_ASYNC16(kb + (uint32_t)(r * SC_PAD + c4) * 4, gp);
        }
    };

    load_k(0); CP_COMMIT();
    __syncthreads();   // Q tile visible

    // ---- preload Q fragments (8 k-steps, m16k8)
    uint32_t aq_off = ((uint32_t)(mbase + (lane & 15)) * SC_PAD + (lane >> 4) * 4) * 4;
    uint32_t qf[8][4];
    #pragma unroll
    for (int s = 0; s < 8; s++)
        ldsm_x4(qf[s][0], qf[s][1], qf[s][2], qf[s][3], sb + aq_off + (uint32_t)(s * 8) * 4);

    uint32_t bk_off = ((uint32_t)(n_warp * 64 + ((lane >> 4) * 8) + (lane & 7)) * SC_PAD
                     + ((lane >> 3) & 1) * 4) * 4;

    const float scl = rsqrtf((float)D);

    // ---- compute one 128-key chunk into acc[8][4] (8 independent chains)
    float acc[8][4];
    auto compute_chunk = [&](int c) {
        #pragma unroll
        for (int ni = 0; ni < 8; ni++)
            #pragma unroll
            for (int r = 0; r < 4; r++) acc[ni][r] = 0.0f;
        uint32_t kb = sb + (QWORDS + (c & 1) * KCH_WORDS) * 4;
        #pragma unroll
        for (int s = 0; s < 8; s++) {
            uint32_t bk[4][4];
            #pragma unroll
            for (int np = 0; np < 4; np++)
                ldsm_x4(bk[np][0], bk[np][1], bk[np][2], bk[np][3],
                        kb + bk_off + (uint32_t)(np * 16 * SC_PAD + s * 8) * 4);
            #pragma unroll
            for (int np = 0; np < 4; np++) {
                mma_tf32(acc[np * 2],     qf[s][0], qf[s][1], qf[s][2], qf[s][3],
                         bk[np][0], bk[np][1]);
                mma_tf32(acc[np * 2 + 1], qf[s][0], qf[s][1], qf[s][2], qf[s][3],
                         bk[np][2], bk[np][3]);
            }
        }
    };

    // =============== PASS 1: online (max, sum) ===============
    float m0 = -1e30f, m1 = -1e30f, s0 = 0.0f, s1 = 0.0f;

    #pragma unroll
    for (int c = 0; c < 8; c++) {
        if (c + 1 < 8) { load_k(c + 1); CP_COMMIT(); }
        if (c + 1 < 8) { CP_WAIT(1); } else { CP_WAIT(0); }
        __syncthreads();
        compute_chunk(c);

        float cm0 = -1e30f, cm1 = -1e30f;
        #pragma unroll
        for (int ni = 0; ni < 8; ni++) {
            cm0 = fmaxf(cm0, fmaxf(acc[ni][0], acc[ni][1]));
            cm1 = fmaxf(cm1, fmaxf(acc[ni][2], acc[ni][3]));
        }
        float nm0 = fmaxf(m0, cm0);
        float nm1 = fmaxf(m1, cm1);
        s0 *= __expf((m0 - nm0) * scl);
        s1 *= __expf((m1 - nm1) * scl);
        #pragma unroll
        for (int ni = 0; ni < 8; ni++) {
            s0 += __expf((acc[ni][0] - nm0) * scl) + __expf((acc[ni][1] - nm0) * scl);
            s1 += __expf((acc[ni][2] - nm1) * scl) + __expf((acc[ni][3] - nm1) * scl);
        }
        m0 = nm0; m1 = nm1;
        __syncthreads();
    }

    // merge across t4 lanes (same row quad)
    #pragma unroll
    for (int o = 1; o <= 2; o <<= 1) {
        float om0 = __shfl_xor_sync(0xffffffffu, m0, o);
        float os0 = __shfl_xor_sync(0xffffffffu, s0, o);
        float om1 = __shfl_xor_sync(0xffffffffu, m1, o);
        float os1 = __shfl_xor_sync(0xffffffffu, s1, o);
        float nm0 = fmaxf(m0, om0), nm1 = fmaxf(m1, om1);
        s0 = s0 * __expf((m0 - nm0) * scl) + os0 * __expf((om0 - nm0) * scl);
        s1 = s1 * __expf((m1 - nm1) * scl) + os1 * __expf((om1 - nm1) * scl);
        m0 = nm0; m1 = nm1;
    }

    // merge across the 2 n_warps via smem
    int row0 = mbase + g4;       // local 0..63
    int row1 = row0 + 8;
    float* redm = smem + SC_RED_OFF;        // [64][2]
    float* reds = smem + SC_RED_OFF + 128;  // [64][2]
    if (t4 == 0) {
        redm[row0 * 2 + n_warp] = m0;  reds[row0 * 2 + n_warp] = s0;
        redm[row1 * 2 + n_warp] = m1;  reds[row1 * 2 + n_warp] = s1;
    }
    __syncthreads();
    {
        float ma = redm[row0 * 2], mb = redm[row0 * 2 + 1];
        float nm = fmaxf(ma, mb);
        float ss = reds[row0 * 2] * __expf((ma - nm) * scl)
                 + reds[row0 * 2 + 1] * __expf((mb - nm) * scl);
        m0 = nm; s0 = 1.0f / ss;
        ma = redm[row1 * 2]; mb = redm[row1 * 2 + 1];
        nm = fmaxf(ma, mb);
        ss = reds[row1 * 2] * __expf((ma - nm) * scl)
           + reds[row1 * 2 + 1] * __expf((mb - nm) * scl);
        m1 = nm; s1 = 1.0f / ss;
    }
    __syncthreads();

    // =============== PASS 2: recompute, normalize, store ===============
    float* o0 = attn + (size_t)bh * SEQ * SEQ + (size_t)(ib + row0) * SEQ;
    float* o1 = attn + (size_t)bh * SEQ * SEQ + (size_t)(ib + row1) * SEQ;

    load_k(0); CP_COMMIT();
    #pragma unroll
    for (int c = 0; c < 8; c++) {
        if (c + 1 < 8) { load_k(c + 1); CP_COMMIT(); }
        if (c + 1 < 8) { CP_WAIT(1); } else { CP_WAIT(0); }
        __syncthreads();
        compute_chunk(c);

        #pragma unroll
        for (int ni = 0; ni < 8; ni++) {
            int col = c * 128 + n_warp * 64 + ni * 8 + t4 * 2;
            float2 p0, p1;
            p0.x = __expf((acc[ni][0] - m0) * scl) * s0;
            p0.y = __expf((acc[ni][1] - m0) * scl) * s0;
            p1.x = __expf((acc[ni][2] - m1) * scl) * s1;
            p1.y = __expf((acc[ni][3] - m1) * scl) * s1;
            *(float2*)(o0 + col) = p0;
            *(float2*)(o1 + col) = p1;
        }
        __syncthreads();
    }
}

// ===========================================================================
// Launch
// ===========================================================================
extern "C" void kernel_launch(void* const* d_in, const int* in_sizes, int n_in,
                              void* d_out, int out_size)
{
    const float* x     = (const float*)d_in[0];
    const float* Wq    = (const float*)d_in[1];
    const float* Wk    = (const float*)d_in[2];
    /* d_in[3] = Wv: DEAD in the reference (attended values are discarded). */
    const float* ln1_s = (const float*)d_in[4];
    const float* ln1_b = (const float*)d_in[5];
    const float* ln2_s = (const float*)d_in[6];
    const float* ln2_b = (const float*)d_in[7];
    const float* ff1_w = (const float*)d_in[8];
    const float* ff1_b = (const float*)d_in[9];
    const float* ff2_w = (const float*)d_in[10];
    const float* ff2_b = (const float*)d_in[11];

    float* out  = (float*)d_out;                       // [4,1024,2048]
    float* attn = out + (size_t)NROWS * D;             // [4,32,1024,1024]

    float *h, *x2, *qk, *h2, *t, *wqkt, *f1t, *f2t;
    cudaGetSymbolAddress((void**)&h,    g_h);
    cudaGetSymbolAddress((void**)&x2,   g_x2);
    cudaGetSymbolAddress((void**)&qk,   g_qk);
    cudaGetSymbolAddress((void**)&h2,   g_h2);
    cudaGetSymbolAddress((void**)&t,    g_t);
    cudaGetSymbolAddress((void**)&wqkt, g_wqkt);
    cudaGetSymbolAddress((void**)&f1t,  g_f1t);
    cudaGetSymbolAddress((void**)&f2t,  g_f2t);

    cudaFuncSetAttribute(gemm_tf32_kernel,
                         cudaFuncAttributeMaxDynamicSharedMemorySize, GEMM_SMEM);
    cudaFuncSetAttribute(scores_softmax_kernel,
                         cudaFuncAttributeMaxDynamicSharedMemorySize, SC_SMEM);

    // Transpose + tf32-round all 4 weights in one launch
    dim3 tg(D / 32, D / 32, 4);
    transpose_round4_kernel<<<tg, 256>>>(Wq, Wk, ff1_w, ff2_w,
                                         wqkt, wqkt + (size_t)D * D, f1t, f2t);

    // LN1
    ln_kernel<<<NROWS, 256>>>(x, ln1_s, ln1_b, h, x2);

    // [q|k] = h @ [Wq|Wk]  (one N=4096 GEMM)
    dim3 gqk(2 * D / BN, NROWS / BM);             // (32, 32)
    gemm_tf32_kernel<<<gqk, 256, GEMM_SMEM>>>(h, wqkt, qk, nullptr, nullptr, 2 * D, 0);

    // fused two-pass scores + softmax -> attn
    dim3 gsc(SEQ / SC_ROWS, NBATCH * NHEADS);     // (16, 128)
    scores_softmax_kernel<<<gsc, 256, SC_SMEM>>>(qk, attn);

    // LN2
    ln_kernel<<<NROWS, 256>>>(x2, ln2_s, ln2_b, h2, nullptr);

    // FF
    dim3 gff(D / BN, NROWS / BM);                 // (16, 32)
    gemm_tf32_kernel<<<gff, 256, GEMM_SMEM>>>(h2, f1t, t, ff1_b, nullptr, D, 1);
    gemm_tf32_kernel<<<gff, 256, GEMM_SMEM>>>(t, f2t, out, ff2_b, x2, D, 2);
}